// round 1
// baseline (speedup 1.0000x reference)
#include <cuda_runtime.h>

// ---------------- problem constants ----------------
constexpr int cB    = 256;
constexpr int cNPG  = 28;
constexpr int cMAXN = 32;
constexpr int cEPG  = 64;
constexpr int cD    = 128;
constexpr int cSK   = 64;
constexpr int cN    = 2 * cB * cNPG;   // 14336 nodes
constexpr int cE    = 2 * cB * cEPG;   // 32768 edges
constexpr int cH    = 256;             // hidden width of msg/upd MLPs
constexpr int TM    = 32;              // rows per MLP tile
constexpr int KC    = 8;               // K chunk

// ---------------- scratch (device globals; no allocation allowed) ----------------
__device__ float g_h[cN * cD];
__device__ float g_e[cE * cD];
__device__ float g_agg[cN * cD];
__device__ float g_em[cE * cD];
__device__ float g_tqc[cB * 2 * cMAXN * cSK];
__device__ float g_plan[cB * cMAXN * cMAXN];

// ---------------- helpers ----------------
__device__ __forceinline__ float warp_max(float v) {
#pragma unroll
    for (int o = 16; o > 0; o >>= 1) v = fmaxf(v, __shfl_xor_sync(0xffffffffu, v, o));
    return v;
}
__device__ __forceinline__ float warp_sum(float v) {
#pragma unroll
    for (int o = 16; o > 0; o >>= 1) v += __shfl_xor_sync(0xffffffffu, v, o);
    return v;
}

// ---------------- encoders: y = x @ W + b  (fin=32 -> 128) ----------------
__global__ void encode_kernel(const float* __restrict__ x, const float* __restrict__ W,
                              const float* __restrict__ bias, int which) {
    int r = blockIdx.x;
    int d = threadIdx.x;  // 128
    __shared__ float sx[32];
    if (d < 32) sx[d] = x[r * 32 + d];
    __syncthreads();
    float acc = bias[d];
#pragma unroll
    for (int k = 0; k < 32; k++) acc = fmaf(sx[k], W[k * cD + d], acc);
    if (which == 0) g_h[r * cD + d] = acc;
    else            g_e[r * cD + d] = acc;
}

__global__ void zero_agg_kernel() {
    int i = blockIdx.x * blockDim.x + threadIdx.x;
    if (i < cN * cD) g_agg[i] = 0.f;
}

// ---------------- fused 2-layer MLP ----------------
// GATHER==0 (edges): X = [h[ia], h[ib], e], K1=384
// GATHER==1 (nodes): X = [agg[n], h[n]],   K1=256
// mode: 0 atomicAdd into g_agg via scat; 1 store g_em; 2 add g_em; 3 add into g_h
template <int K1, int GATHER>
__global__ void __launch_bounds__(256) mlp_kernel(
    const int* __restrict__ ia, const int* __restrict__ ib,
    const float* __restrict__ W1, const float* __restrict__ b1p,
    const float* __restrict__ W2, const float* __restrict__ b2p,
    const int* __restrict__ scat, int mode) {
    __shared__ float sA[KC][TM];
    __shared__ float sB[KC][cH];      // also reused for W2 chunks
    __shared__ float sHid[TM][cH];
    __shared__ int sIa[TM], sIb[TM], sSc[TM];

    const int tid = threadIdx.x;
    const int e0 = blockIdx.x * TM;
    if (tid < TM) {
        if (GATHER == 0) { sIa[tid] = ia[e0 + tid]; sIb[tid] = ib[e0 + tid]; }
        sSc[tid] = scat ? scat[e0 + tid] : 0;
    }
    __syncthreads();

    float acc[4][8];
#pragma unroll
    for (int i = 0; i < 4; i++)
#pragma unroll
        for (int j = 0; j < 8; j++) acc[i][j] = 0.f;

    const int r_ld = tid >> 3, k_ld = tid & 7;
    const int ty = tid >> 5, tx = tid & 31;
    const int r0 = ty * 4, c0 = tx * 4;

    // ---- stage 1: hidden = relu(X @ W1 + b1) ----
    for (int k0 = 0; k0 < K1; k0 += KC) {
        {
            int k = k0 + k_ld;
            float v;
            if (GATHER == 0) {
                if (k < cD)          v = g_h[sIa[r_ld] * cD + k];
                else if (k < 2 * cD) v = g_h[sIb[r_ld] * cD + (k - cD)];
                else                 v = g_e[(e0 + r_ld) * cD + (k - 2 * cD)];
            } else {
                if (k < cD)          v = g_agg[(e0 + r_ld) * cD + k];
                else                 v = g_h[(e0 + r_ld) * cD + (k - cD)];
            }
            sA[k_ld][r_ld] = v;
        }
        {
            const float4* src = reinterpret_cast<const float4*>(W1 + k0 * cH);
            float4* dst = reinterpret_cast<float4*>(&sB[0][0]);
            dst[2 * tid]     = src[2 * tid];
            dst[2 * tid + 1] = src[2 * tid + 1];
        }
        __syncthreads();
#pragma unroll
        for (int kk = 0; kk < KC; kk++) {
            float a0 = sA[kk][r0 + 0], a1 = sA[kk][r0 + 1];
            float a2 = sA[kk][r0 + 2], a3 = sA[kk][r0 + 3];
            float4 bl = *reinterpret_cast<const float4*>(&sB[kk][c0]);
            float4 bh = *reinterpret_cast<const float4*>(&sB[kk][c0 + cD]);
            float bb[8] = {bl.x, bl.y, bl.z, bl.w, bh.x, bh.y, bh.z, bh.w};
#pragma unroll
            for (int j = 0; j < 8; j++) {
                acc[0][j] = fmaf(a0, bb[j], acc[0][j]);
                acc[1][j] = fmaf(a1, bb[j], acc[1][j]);
                acc[2][j] = fmaf(a2, bb[j], acc[2][j]);
                acc[3][j] = fmaf(a3, bb[j], acc[3][j]);
            }
        }
        __syncthreads();
    }
    {
        float4 bl = *reinterpret_cast<const float4*>(b1p + c0);
        float4 bh = *reinterpret_cast<const float4*>(b1p + c0 + cD);
        float bb[8] = {bl.x, bl.y, bl.z, bl.w, bh.x, bh.y, bh.z, bh.w};
#pragma unroll
        for (int i = 0; i < 4; i++) {
            float4 lo = make_float4(fmaxf(acc[i][0] + bb[0], 0.f), fmaxf(acc[i][1] + bb[1], 0.f),
                                    fmaxf(acc[i][2] + bb[2], 0.f), fmaxf(acc[i][3] + bb[3], 0.f));
            float4 hi = make_float4(fmaxf(acc[i][4] + bb[4], 0.f), fmaxf(acc[i][5] + bb[5], 0.f),
                                    fmaxf(acc[i][6] + bb[6], 0.f), fmaxf(acc[i][7] + bb[7], 0.f));
            *reinterpret_cast<float4*>(&sHid[r0 + i][c0])      = lo;
            *reinterpret_cast<float4*>(&sHid[r0 + i][c0 + cD]) = hi;
        }
    }
    __syncthreads();

    // ---- stage 2: out = hidden @ W2 + b2 ----
    float acc2[4][4];
#pragma unroll
    for (int i = 0; i < 4; i++)
#pragma unroll
        for (int j = 0; j < 4; j++) acc2[i][j] = 0.f;

    float* sW2 = &sB[0][0];  // KC*cD floats
    for (int k0 = 0; k0 < cH; k0 += KC) {
        reinterpret_cast<float4*>(sW2)[tid] = reinterpret_cast<const float4*>(W2 + k0 * cD)[tid];
        __syncthreads();
#pragma unroll
        for (int kk = 0; kk < KC; kk++) {
            float4 bv = *reinterpret_cast<const float4*>(&sW2[kk * cD + c0]);
            float a0 = sHid[r0 + 0][k0 + kk], a1 = sHid[r0 + 1][k0 + kk];
            float a2 = sHid[r0 + 2][k0 + kk], a3 = sHid[r0 + 3][k0 + kk];
            acc2[0][0] = fmaf(a0, bv.x, acc2[0][0]); acc2[0][1] = fmaf(a0, bv.y, acc2[0][1]);
            acc2[0][2] = fmaf(a0, bv.z, acc2[0][2]); acc2[0][3] = fmaf(a0, bv.w, acc2[0][3]);
            acc2[1][0] = fmaf(a1, bv.x, acc2[1][0]); acc2[1][1] = fmaf(a1, bv.y, acc2[1][1]);
            acc2[1][2] = fmaf(a1, bv.z, acc2[1][2]); acc2[1][3] = fmaf(a1, bv.w, acc2[1][3]);
            acc2[2][0] = fmaf(a2, bv.x, acc2[2][0]); acc2[2][1] = fmaf(a2, bv.y, acc2[2][1]);
            acc2[2][2] = fmaf(a2, bv.z, acc2[2][2]); acc2[2][3] = fmaf(a2, bv.w, acc2[2][3]);
            acc2[3][0] = fmaf(a3, bv.x, acc2[3][0]); acc2[3][1] = fmaf(a3, bv.y, acc2[3][1]);
            acc2[3][2] = fmaf(a3, bv.z, acc2[3][2]); acc2[3][3] = fmaf(a3, bv.w, acc2[3][3]);
        }
        __syncthreads();
    }
    float4 b2v = *reinterpret_cast<const float4*>(b2p + c0);
    float bb2[4] = {b2v.x, b2v.y, b2v.z, b2v.w};

    if (mode == 0) {
#pragma unroll
        for (int i = 0; i < 4; i++) {
            int nidx = sSc[r0 + i];
#pragma unroll
            for (int j = 0; j < 4; j++)
                atomicAdd(&g_agg[nidx * cD + c0 + j], acc2[i][j] + bb2[j]);
        }
    } else if (mode == 1) {
#pragma unroll
        for (int i = 0; i < 4; i++)
#pragma unroll
            for (int j = 0; j < 4; j++)
                g_em[(e0 + r0 + i) * cD + c0 + j] = acc2[i][j] + bb2[j];
    } else if (mode == 2) {
#pragma unroll
        for (int i = 0; i < 4; i++)
#pragma unroll
            for (int j = 0; j < 4; j++)
                g_em[(e0 + r0 + i) * cD + c0 + j] += acc2[i][j] + bb2[j];
    } else {
#pragma unroll
        for (int i = 0; i < 4; i++)
#pragma unroll
            for (int j = 0; j < 4; j++)
                g_h[(e0 + r0 + i) * cD + c0 + j] += acc2[i][j] + bb2[j];
    }
}

// ---------------- SK head: t = relu(x@w1+b1)@w2+b2, masked ----------------
// grid: (B*2*MAXN)/4 blocks of 256 threads; 4 rows per block
__global__ void __launch_bounds__(256) sk_kernel(
    const float* __restrict__ w1p, const float* __restrict__ b1p,
    const float* __restrict__ w2p, const float* __restrict__ b2p,
    const int* __restrict__ qs, const int* __restrict__ cs) {
    int t = threadIdx.x;
    int lr = t >> 6;      // local row 0..3
    int j  = t & 63;      // output dim
    int row = blockIdx.x * 4 + lr;  // b*64 + s*32 + p
    int b = row >> 6;
    int sp = row & 63;
    int s = sp >> 5;
    int p = sp & 31;
    __shared__ float sx[4][128];
    __shared__ float sh[4][64];
    {
        bool valid = p < cNPG;
        int node = (b * 2 + s) * cNPG + p;
        sx[lr][j]      = valid ? g_h[node * cD + j]      : 0.f;
        sx[lr][j + 64] = valid ? g_h[node * cD + j + 64] : 0.f;
    }
    __syncthreads();
    float a = b1p[j];
#pragma unroll
    for (int k = 0; k < 128; k++) a = fmaf(sx[lr][k], w1p[k * 64 + j], a);
    sh[lr][j] = fmaxf(a, 0.f);
    __syncthreads();
    float o = b2p[j];
#pragma unroll
    for (int k = 0; k < 64; k++) o = fmaf(sh[lr][k], w2p[k * 64 + j], o);
    int size = (s == 0) ? qs[b] : cs[b];
    if (p >= size) o = 0.f;
    g_tqc[row * 64 + j] = o;
}

// ---------------- node scores + Sinkhorn -> g_plan ----------------
__global__ void __launch_bounds__(1024) node_plan_kernel() {
    int b = blockIdx.x;
    int tid = threadIdx.x;
    __shared__ float smq[32][65];
    __shared__ float smc[32][65];
    __shared__ float la[32 * 33];
    for (int idx = tid; idx < 2048; idx += 1024) {
        int r = idx >> 6, d = idx & 63;
        smq[r][d] = g_tqc[b * 4096 + idx];
        smc[r][d] = g_tqc[b * 4096 + 2048 + idx];
    }
    __syncthreads();
    int q = tid >> 5, c = tid & 31;
    float v = 0.f;
#pragma unroll
    for (int d = 0; d < 64; d++) v = fmaf(smq[q][d], smc[c][d], v);
    v *= 10.f;  // / TEMP
    for (int it = 0; it < 20; it++) {
        // row (axis=2) normalization: one warp per row
        float m = warp_max(v);
        float sum = warp_sum(expf(v - m));
        v -= m + logf(sum);
        la[q * 33 + c] = v;
        __syncthreads();
        // col (axis=1) normalization: warp q handles column q, lanes are rows
        float u = la[c * 33 + q];
        m = warp_max(u);
        sum = warp_sum(expf(u - m));
        u -= m + logf(sum);
        la[c * 33 + q] = u;
        __syncthreads();
        v = la[q * 33 + c];
    }
    g_plan[b * 1024 + q * 32 + c] = expf(v);
}

// ---------------- node alignment: out[b] = -sum relu(q - plan@c) ----------------
__global__ void __launch_bounds__(256) node_align_kernel(float* __restrict__ out) {
    int b = blockIdx.x, tid = threadIdx.x;
    __shared__ float sp_[32 * 32];
    __shared__ float scn[32][128];
    __shared__ float red[8];
    for (int idx = tid; idx < 1024; idx += 256) sp_[idx] = g_plan[b * 1024 + idx];
    for (int idx = tid; idx < 4096; idx += 256) {
        int p = idx >> 7, d = idx & 127;
        scn[p][d] = (p < cNPG) ? g_h[((b * 2 + 1) * cNPG + p) * cD + d] : 0.f;
    }
    __syncthreads();
    float local = 0.f;
    for (int idx = tid; idx < 4096; idx += 256) {
        int q = idx >> 7, d = idx & 127;
        float pc = 0.f;
#pragma unroll
        for (int c = 0; c < 32; c++) pc = fmaf(sp_[q * 32 + c], scn[c][d], pc);
        float qv = (q < cNPG) ? g_h[((b * 2) * cNPG + q) * cD + d] : 0.f;
        local += fmaxf(qv - pc, 0.f);
    }
    local = warp_sum(local);
    if ((tid & 31) == 0) red[tid >> 5] = local;
    __syncthreads();
    if (tid == 0) {
        float tot = 0.f;
        for (int i = 0; i < 8; i++) tot += red[i];
        out[b] = -tot;
    }
}

// ---------------- edge kron + Sinkhorn + alignment (fused per b) ----------------
__global__ void __launch_bounds__(1024) edge_kernel(
    const int* __restrict__ from_idx, const int* __restrict__ to_idx,
    float* __restrict__ out) {
    int b = blockIdx.x, tid = threadIdx.x;
    __shared__ float T[32 * 32];
    __shared__ float la[64][65];
    __shared__ int qf[64], qt[64], cf[64], ct[64];
    __shared__ float red[32];

    T[tid & 1023] = g_plan[b * 1024 + (tid & 1023)];
    if (tid < 64) {
        qf[tid] = from_idx[b * 128 + tid] % cNPG;
        qt[tid] = to_idx[b * 128 + tid] % cNPG;
        cf[tid] = from_idx[b * 128 + 64 + tid] % cNPG;
        ct[tid] = to_idx[b * 128 + 64 + tid] % cNPG;
    }
    __syncthreads();
    for (int idx = tid; idx < 4096; idx += 1024) {
        int i = idx >> 6, j = idx & 63;
        float s = T[qf[i] * 32 + cf[j]] * T[qt[i] * 32 + ct[j]]
                + T[qf[i] * 32 + ct[j]] * T[qt[i] * 32 + cf[j]];
        la[i][j] = s * 10.f;  // / TEMP
    }
    __syncthreads();
    int w = tid >> 5, l = tid & 31;
    for (int it = 0; it < 20; it++) {
#pragma unroll
        for (int rr_ = 0; rr_ < 2; rr_++) {
            int rr = w + rr_ * 32;
            float v0 = la[rr][l], v1 = la[rr][l + 32];
            float m = warp_max(fmaxf(v0, v1));
            float s = warp_sum(expf(v0 - m) + expf(v1 - m));
            float lse = m + logf(s);
            la[rr][l] = v0 - lse;
            la[rr][l + 32] = v1 - lse;
        }
        __syncthreads();
#pragma unroll
        for (int cc_ = 0; cc_ < 2; cc_++) {
            int cc = w + cc_ * 32;
            float v0 = la[l][cc], v1 = la[l + 32][cc];
            float m = warp_max(fmaxf(v0, v1));
            float s = warp_sum(expf(v0 - m) + expf(v1 - m));
            float lse = m + logf(s);
            la[l][cc] = v0 - lse;
            la[l + 32][cc] = v1 - lse;
        }
        __syncthreads();
    }
    for (int idx = tid; idx < 4096; idx += 1024) {
        int i = idx >> 6, j = idx & 63;
        la[i][j] = expf(la[i][j]);
    }
    __syncthreads();
    float local = 0.f;
    for (int idx = tid; idx < 8192; idx += 1024) {
        int i = idx >> 7, d = idx & 127;
        const float* ce = &g_em[(b * 128 + 64) * cD + d];
        float pc = 0.f;
#pragma unroll
        for (int j = 0; j < 64; j++) pc = fmaf(la[i][j], ce[j * cD], pc);
        float qv = g_em[(b * 128 + i) * cD + d];
        local += fmaxf(qv - pc, 0.f);
    }
    local = warp_sum(local);
    if (l == 0) red[w] = local;
    __syncthreads();
    if (tid == 0) {
        float tot = 0.f;
        for (int i = 0; i < 32; i++) tot += red[i];
        out[b] += -0.9f * tot;  // CW
    }
}

// ---------------- launch ----------------
extern "C" void kernel_launch(void* const* d_in, const int* in_sizes, int n_in,
                              void* d_out, int out_size) {
    const float* nf      = (const float*)d_in[0];
    const float* ef      = (const float*)d_in[1];
    const float* enc_nw  = (const float*)d_in[2];
    const float* enc_nb  = (const float*)d_in[3];
    const float* enc_ew  = (const float*)d_in[4];
    const float* enc_eb  = (const float*)d_in[5];
    const float* msg_w1  = (const float*)d_in[6];
    const float* msg_b1  = (const float*)d_in[7];
    const float* msg_w2  = (const float*)d_in[8];
    const float* msg_b2  = (const float*)d_in[9];
    const float* rmsg_w1 = (const float*)d_in[10];
    const float* rmsg_b1 = (const float*)d_in[11];
    const float* rmsg_w2 = (const float*)d_in[12];
    const float* rmsg_b2 = (const float*)d_in[13];
    const float* upd_w1  = (const float*)d_in[14];
    const float* upd_b1  = (const float*)d_in[15];
    const float* upd_w2  = (const float*)d_in[16];
    const float* upd_b2  = (const float*)d_in[17];
    const float* sk_w1   = (const float*)d_in[18];
    const float* sk_b1   = (const float*)d_in[19];
    const float* sk_w2   = (const float*)d_in[20];
    const float* sk_b2   = (const float*)d_in[21];
    const int* from_idx  = (const int*)d_in[22];
    const int* to_idx    = (const int*)d_in[23];
    const int* qs        = (const int*)d_in[24];
    const int* cs        = (const int*)d_in[25];
    float* out = (float*)d_out;

    // encode
    encode_kernel<<<cN, 128>>>(nf, enc_nw, enc_nb, 0);
    encode_kernel<<<cE, 128>>>(ef, enc_ew, enc_eb, 1);

    // 3 message-passing steps
    for (int step = 0; step < 3; step++) {
        zero_agg_kernel<<<(cN * cD + 1023) / 1024, 1024>>>();
        mlp_kernel<384, 0><<<cE / TM, 256>>>(from_idx, to_idx, msg_w1, msg_b1, msg_w2, msg_b2, to_idx, 0);
        mlp_kernel<384, 0><<<cE / TM, 256>>>(to_idx, from_idx, rmsg_w1, rmsg_b1, rmsg_w2, rmsg_b2, from_idx, 0);
        mlp_kernel<256, 1><<<cN / TM, 256>>>(nullptr, nullptr, upd_w1, upd_b1, upd_w2, upd_b2, nullptr, 3);
    }

    // final messages -> em = f + r
    mlp_kernel<384, 0><<<cE / TM, 256>>>(from_idx, to_idx, msg_w1, msg_b1, msg_w2, msg_b2, nullptr, 1);
    mlp_kernel<384, 0><<<cE / TM, 256>>>(to_idx, from_idx, rmsg_w1, rmsg_b1, rmsg_w2, rmsg_b2, nullptr, 2);

    // SK head, node plan, node align, edge (kron+sinkhorn+align)
    sk_kernel<<<cB * 2 * cMAXN / 4, 256>>>(sk_w1, sk_b1, sk_w2, sk_b2, qs, cs);
    node_plan_kernel<<<cB, 1024>>>();
    node_align_kernel<<<cB, 256>>>(out);
    edge_kernel<<<cB, 1024>>>(from_idx, to_idx, out);
}

// round 2
// speedup vs baseline: 1.2052x; 1.2052x over previous
#include <cuda_runtime.h>

// ---------------- problem constants ----------------
constexpr int cB    = 256;
constexpr int cNPG  = 28;
constexpr int cMAXN = 32;
constexpr int cD    = 128;
constexpr int cSK   = 64;
constexpr int cN    = 2 * cB * cNPG;   // 14336 nodes
constexpr int cE    = 2 * cB * 64;     // 32768 edges
constexpr int cH    = 256;             // hidden width of msg/upd MLPs
constexpr int TM    = 32;              // rows per MLP tile
constexpr int KC    = 8;               // K chunk

// ---------------- scratch (device globals; no allocation allowed) ----------------
__device__ float g_h[cN * cD];
__device__ float g_e[cE * cD];
__device__ float g_agg[cN * cD];
__device__ float g_em[cE * cD];
__device__ float g_tqc[cB * 2 * cMAXN * cSK];
__device__ float g_plan[cB * cMAXN * cMAXN];

typedef unsigned long long u64;

// ---------------- packed fp32 FMA (Blackwell FFMA2, PTX-only) ----------------
__device__ __forceinline__ u64 pack2(float lo, float hi) {
    u64 r; asm("mov.b64 %0,{%1,%2};" : "=l"(r) : "f"(lo), "f"(hi)); return r;
}
__device__ __forceinline__ void fma2(u64& d, u64 a, u64 b) {
    asm("fma.rn.f32x2 %0,%1,%2,%0;" : "+l"(d) : "l"(a), "l"(b));
}
__device__ __forceinline__ float2 unpack2(u64 v) {
    float2 f; asm("mov.b64 {%0,%1},%2;" : "=f"(f.x), "=f"(f.y) : "l"(v)); return f;
}

// ---------------- helpers ----------------
__device__ __forceinline__ float warp_max(float v) {
#pragma unroll
    for (int o = 16; o > 0; o >>= 1) v = fmaxf(v, __shfl_xor_sync(0xffffffffu, v, o));
    return v;
}
__device__ __forceinline__ float warp_sum(float v) {
#pragma unroll
    for (int o = 16; o > 0; o >>= 1) v += __shfl_xor_sync(0xffffffffu, v, o);
    return v;
}

// ---------------- encoders: y = x @ W + b  (fin=32 -> 128) ----------------
__global__ void encode_kernel(const float* __restrict__ x, const float* __restrict__ W,
                              const float* __restrict__ bias, int which) {
    int r = blockIdx.x;
    int d = threadIdx.x;  // 128
    __shared__ float sx[32];
    if (d < 32) sx[d] = x[r * 32 + d];
    __syncthreads();
    float acc = bias[d];
#pragma unroll
    for (int k = 0; k < 32; k++) acc = fmaf(sx[k], W[k * cD + d], acc);
    if (which == 0) g_h[r * cD + d] = acc;
    else            g_e[r * cD + d] = acc;
}

__global__ void zero_agg_kernel() {
    int i = blockIdx.x * blockDim.x + threadIdx.x;
    if (i < cN * cD) g_agg[i] = 0.f;
}

// ---------------- fused 2-layer MLP, 8x8 register tile + FFMA2 ----------------
// GATHER==0 (edges): X = [h[ia], h[ib], e], K1=384
// GATHER==1 (nodes): X = [agg[n], h[n]],   K1=256
// mode: 0 atomicAdd into g_agg via scat; 1 store g_em; 2 add g_em; 3 add into g_h
template <int K1, int GATHER>
__global__ void __launch_bounds__(128, 3) mlp_kernel(
    const int* __restrict__ ia, const int* __restrict__ ib,
    const float* __restrict__ W1, const float* __restrict__ b1p,
    const float* __restrict__ W2, const float* __restrict__ b2p,
    const int* __restrict__ scat, int mode) {
    __shared__ float sA[KC][TM];
    __shared__ float sB[KC][cH];      // W1 chunk; reused for W2 chunks
    __shared__ float sHid[TM][cH];
    __shared__ int sIa[TM], sIb[TM], sSc[TM];

    const int tid = threadIdx.x;
    const int e0 = blockIdx.x * TM;
    if (tid < TM) {
        if (GATHER == 0) { sIa[tid] = ia[e0 + tid]; sIb[tid] = ib[e0 + tid]; }
        sSc[tid] = scat ? scat[e0 + tid] : 0;
    }
    __syncthreads();

    // stage-1 mapping: 4 row-groups x 32 col-groups, each thread 8 rows x 8 cols
    const int ty = tid >> 5, tx = tid & 31;
    const int r0 = ty * 8, c0 = tx * 8;

    u64 acc[8][4];
#pragma unroll
    for (int i = 0; i < 8; i++)
#pragma unroll
        for (int j = 0; j < 4; j++) acc[i][j] = 0ull;

    // ---- stage 1: hidden = relu(X @ W1 + b1) ----
    for (int k0 = 0; k0 < K1; k0 += KC) {
        if (tid < 64) {
            int r = tid >> 1, q = tid & 1;
            int k = k0 + q * 4;
            const float* src;
            if (GATHER == 0) {
                if (k < cD)          src = g_h + sIa[r] * cD + k;
                else if (k < 2 * cD) src = g_h + sIb[r] * cD + (k - cD);
                else                 src = g_e + (e0 + r) * cD + (k - 2 * cD);
            } else {
                if (k < cD)          src = g_agg + (e0 + r) * cD + k;
                else                 src = g_h + (e0 + r) * cD + (k - cD);
            }
            float4 v = *reinterpret_cast<const float4*>(src);
            int kb = q * 4;
            sA[kb + 0][r] = v.x; sA[kb + 1][r] = v.y;
            sA[kb + 2][r] = v.z; sA[kb + 3][r] = v.w;
        }
        {
            const float4* src = reinterpret_cast<const float4*>(W1 + (size_t)k0 * cH);
            float4* dst = reinterpret_cast<float4*>(&sB[0][0]);
#pragma unroll
            for (int i = 0; i < 4; i++) dst[i * 128 + tid] = src[i * 128 + tid];
        }
        __syncthreads();
#pragma unroll
        for (int kk = 0; kk < KC; kk++) {
            float4 alo = *reinterpret_cast<const float4*>(&sA[kk][r0]);
            float4 ahi = *reinterpret_cast<const float4*>(&sA[kk][r0 + 4]);
            u64 av[8];
            av[0] = pack2(alo.x, alo.x); av[1] = pack2(alo.y, alo.y);
            av[2] = pack2(alo.z, alo.z); av[3] = pack2(alo.w, alo.w);
            av[4] = pack2(ahi.x, ahi.x); av[5] = pack2(ahi.y, ahi.y);
            av[6] = pack2(ahi.z, ahi.z); av[7] = pack2(ahi.w, ahi.w);
            float4 b0 = *reinterpret_cast<const float4*>(&sB[kk][c0]);
            float4 b1 = *reinterpret_cast<const float4*>(&sB[kk][c0 + 4]);
            u64 bv[4];
            bv[0] = pack2(b0.x, b0.y); bv[1] = pack2(b0.z, b0.w);
            bv[2] = pack2(b1.x, b1.y); bv[3] = pack2(b1.z, b1.w);
#pragma unroll
            for (int i = 0; i < 8; i++)
#pragma unroll
                for (int j = 0; j < 4; j++) fma2(acc[i][j], av[i], bv[j]);
        }
        __syncthreads();
    }
    // bias + relu -> sHid
    {
        float4 blo = *reinterpret_cast<const float4*>(b1p + c0);
        float4 bhi = *reinterpret_cast<const float4*>(b1p + c0 + 4);
#pragma unroll
        for (int i = 0; i < 8; i++) {
            float2 p0 = unpack2(acc[i][0]);
            float2 p1 = unpack2(acc[i][1]);
            float2 p2 = unpack2(acc[i][2]);
            float2 p3 = unpack2(acc[i][3]);
            float4 lo = make_float4(fmaxf(p0.x + blo.x, 0.f), fmaxf(p0.y + blo.y, 0.f),
                                    fmaxf(p1.x + blo.z, 0.f), fmaxf(p1.y + blo.w, 0.f));
            float4 hi = make_float4(fmaxf(p2.x + bhi.x, 0.f), fmaxf(p2.y + bhi.y, 0.f),
                                    fmaxf(p3.x + bhi.z, 0.f), fmaxf(p3.y + bhi.w, 0.f));
            *reinterpret_cast<float4*>(&sHid[r0 + i][c0])     = lo;
            *reinterpret_cast<float4*>(&sHid[r0 + i][c0 + 4]) = hi;
        }
    }

    // ---- stage 2: out = hidden @ W2 + b2 ----
    // mapping: 8 row-groups x 16 col-groups, each thread 4 rows x 8 cols
    const int ty2 = tid >> 4, tx2 = tid & 15;
    const int r2 = ty2 * 4, c2 = tx2 * 8;
    u64 acc2[4][4];
#pragma unroll
    for (int i = 0; i < 4; i++)
#pragma unroll
        for (int j = 0; j < 4; j++) acc2[i][j] = 0ull;

    float* sW2 = &sB[0][0];  // [KC][cD]
    for (int k0 = 0; k0 < cH; k0 += KC) {
        {
            const float4* src = reinterpret_cast<const float4*>(W2 + (size_t)k0 * cD);
            float4* dst = reinterpret_cast<float4*>(sW2);
#pragma unroll
            for (int i = 0; i < 2; i++) dst[i * 128 + tid] = src[i * 128 + tid];
        }
        __syncthreads();
#pragma unroll
        for (int kk = 0; kk < KC; kk++) {
            u64 av[4];
#pragma unroll
            for (int i = 0; i < 4; i++) {
                float a = sHid[r2 + i][k0 + kk];
                av[i] = pack2(a, a);
            }
            const float* w2row = sW2 + kk * cD;
            float4 b0 = *reinterpret_cast<const float4*>(w2row + c2);
            float4 b1 = *reinterpret_cast<const float4*>(w2row + c2 + 4);
            u64 bv[4];
            bv[0] = pack2(b0.x, b0.y); bv[1] = pack2(b0.z, b0.w);
            bv[2] = pack2(b1.x, b1.y); bv[3] = pack2(b1.z, b1.w);
#pragma unroll
            for (int i = 0; i < 4; i++)
#pragma unroll
                for (int j = 0; j < 4; j++) fma2(acc2[i][j], av[i], bv[j]);
        }
        __syncthreads();
    }

    float4 blo2 = *reinterpret_cast<const float4*>(b2p + c2);
    float4 bhi2 = *reinterpret_cast<const float4*>(b2p + c2 + 4);
    float bb2[8] = {blo2.x, blo2.y, blo2.z, blo2.w, bhi2.x, bhi2.y, bhi2.z, bhi2.w};

#pragma unroll
    for (int i = 0; i < 4; i++) {
        float o[8];
        float2 p0 = unpack2(acc2[i][0]);
        float2 p1 = unpack2(acc2[i][1]);
        float2 p2 = unpack2(acc2[i][2]);
        float2 p3 = unpack2(acc2[i][3]);
        o[0] = p0.x + bb2[0]; o[1] = p0.y + bb2[1];
        o[2] = p1.x + bb2[2]; o[3] = p1.y + bb2[3];
        o[4] = p2.x + bb2[4]; o[5] = p2.y + bb2[5];
        o[6] = p3.x + bb2[6]; o[7] = p3.y + bb2[7];
        int row = r2 + i;
        if (mode == 0) {
            int nidx = sSc[row];
#pragma unroll
            for (int j = 0; j < 8; j++)
                atomicAdd(&g_agg[nidx * cD + c2 + j], o[j]);
        } else if (mode == 1) {
            float* dst = &g_em[(e0 + row) * cD + c2];
            *reinterpret_cast<float4*>(dst)     = make_float4(o[0], o[1], o[2], o[3]);
            *reinterpret_cast<float4*>(dst + 4) = make_float4(o[4], o[5], o[6], o[7]);
        } else if (mode == 2) {
            float* dst = &g_em[(e0 + row) * cD + c2];
#pragma unroll
            for (int j = 0; j < 8; j++) dst[j] += o[j];
        } else {
            float* dst = &g_h[(e0 + row) * cD + c2];
#pragma unroll
            for (int j = 0; j < 8; j++) dst[j] += o[j];
        }
    }
}

// ---------------- SK head: t = relu(x@w1+b1)@w2+b2, masked ----------------
__global__ void __launch_bounds__(256) sk_kernel(
    const float* __restrict__ w1p, const float* __restrict__ b1p,
    const float* __restrict__ w2p, const float* __restrict__ b2p,
    const int* __restrict__ qs, const int* __restrict__ cs) {
    int t = threadIdx.x;
    int lr = t >> 6;      // local row 0..3
    int j  = t & 63;      // output dim
    int row = blockIdx.x * 4 + lr;  // b*64 + s*32 + p
    int b = row >> 6;
    int sp = row & 63;
    int s = sp >> 5;
    int p = sp & 31;
    __shared__ float sx[4][128];
    __shared__ float sh[4][64];
    {
        bool valid = p < cNPG;
        int node = (b * 2 + s) * cNPG + p;
        sx[lr][j]      = valid ? g_h[node * cD + j]      : 0.f;
        sx[lr][j + 64] = valid ? g_h[node * cD + j + 64] : 0.f;
    }
    __syncthreads();
    float a = b1p[j];
#pragma unroll
    for (int k = 0; k < 128; k++) a = fmaf(sx[lr][k], w1p[k * 64 + j], a);
    sh[lr][j] = fmaxf(a, 0.f);
    __syncthreads();
    float o = b2p[j];
#pragma unroll
    for (int k = 0; k < 64; k++) o = fmaf(sh[lr][k], w2p[k * 64 + j], o);
    int size = (s == 0) ? qs[b] : cs[b];
    if (p >= size) o = 0.f;
    g_tqc[row * 64 + j] = o;
}

// ---------------- node scores + Sinkhorn -> g_plan ----------------
__global__ void __launch_bounds__(1024) node_plan_kernel() {
    int b = blockIdx.x;
    int tid = threadIdx.x;
    __shared__ float smq[32][65];
    __shared__ float smc[32][65];
    __shared__ float la[32 * 33];
    for (int idx = tid; idx < 2048; idx += 1024) {
        int r = idx >> 6, d = idx & 63;
        smq[r][d] = g_tqc[b * 4096 + idx];
        smc[r][d] = g_tqc[b * 4096 + 2048 + idx];
    }
    __syncthreads();
    int q = tid >> 5, c = tid & 31;
    float v = 0.f;
#pragma unroll
    for (int d = 0; d < 64; d++) v = fmaf(smq[q][d], smc[c][d], v);
    v *= 10.f;  // / TEMP
    for (int it = 0; it < 20; it++) {
        float m = warp_max(v);
        float sum = warp_sum(expf(v - m));
        v -= m + logf(sum);
        la[q * 33 + c] = v;
        __syncthreads();
        float u = la[c * 33 + q];
        m = warp_max(u);
        sum = warp_sum(expf(u - m));
        u -= m + logf(sum);
        la[c * 33 + q] = u;
        __syncthreads();
        v = la[q * 33 + c];
    }
    g_plan[b * 1024 + q * 32 + c] = expf(v);
}

// ---------------- node alignment: out[b] = -sum relu(q - plan@c) ----------------
__global__ void __launch_bounds__(256) node_align_kernel(float* __restrict__ out) {
    int b = blockIdx.x, tid = threadIdx.x;
    __shared__ float sp_[32 * 32];
    __shared__ float scn[32][128];
    __shared__ float red[8];
    for (int idx = tid; idx < 1024; idx += 256) sp_[idx] = g_plan[b * 1024 + idx];
    for (int idx = tid; idx < 4096; idx += 256) {
        int p = idx >> 7, d = idx & 127;
        scn[p][d] = (p < cNPG) ? g_h[((b * 2 + 1) * cNPG + p) * cD + d] : 0.f;
    }
    __syncthreads();
    float local = 0.f;
    for (int idx = tid; idx < 4096; idx += 256) {
        int q = idx >> 7, d = idx & 127;
        float pc = 0.f;
#pragma unroll
        for (int c = 0; c < 32; c++) pc = fmaf(sp_[q * 32 + c], scn[c][d], pc);
        float qv = (q < cNPG) ? g_h[((b * 2) * cNPG + q) * cD + d] : 0.f;
        local += fmaxf(qv - pc, 0.f);
    }
    local = warp_sum(local);
    if ((tid & 31) == 0) red[tid >> 5] = local;
    __syncthreads();
    if (tid == 0) {
        float tot = 0.f;
        for (int i = 0; i < 8; i++) tot += red[i];
        out[b] = -tot;
    }
}

// ---------------- edge kron + Sinkhorn + alignment (fused per b) ----------------
__global__ void __launch_bounds__(1024) edge_kernel(
    const int* __restrict__ from_idx, const int* __restrict__ to_idx,
    float* __restrict__ out) {
    int b = blockIdx.x, tid = threadIdx.x;
    __shared__ float T[32 * 32];
    __shared__ float la[64][65];
    __shared__ int qf[64], qt[64], cf[64], ct[64];
    __shared__ float red[32];

    T[tid & 1023] = g_plan[b * 1024 + (tid & 1023)];
    if (tid < 64) {
        qf[tid] = from_idx[b * 128 + tid] % cNPG;
        qt[tid] = to_idx[b * 128 + tid] % cNPG;
        cf[tid] = from_idx[b * 128 + 64 + tid] % cNPG;
        ct[tid] = to_idx[b * 128 + 64 + tid] % cNPG;
    }
    __syncthreads();
    for (int idx = tid; idx < 4096; idx += 1024) {
        int i = idx >> 6, j = idx & 63;
        float s = T[qf[i] * 32 + cf[j]] * T[qt[i] * 32 + ct[j]]
                + T[qf[i] * 32 + ct[j]] * T[qt[i] * 32 + cf[j]];
        la[i][j] = s * 10.f;  // / TEMP
    }
    __syncthreads();
    int w = tid >> 5, l = tid & 31;
    for (int it = 0; it < 20; it++) {
#pragma unroll
        for (int rr_ = 0; rr_ < 2; rr_++) {
            int rr = w + rr_ * 32;
            float v0 = la[rr][l], v1 = la[rr][l + 32];
            float m = warp_max(fmaxf(v0, v1));
            float s = warp_sum(expf(v0 - m) + expf(v1 - m));
            float lse = m + logf(s);
            la[rr][l] = v0 - lse;
            la[rr][l + 32] = v1 - lse;
        }
        __syncthreads();
#pragma unroll
        for (int cc_ = 0; cc_ < 2; cc_++) {
            int cc = w + cc_ * 32;
            float v0 = la[l][cc], v1 = la[l + 32][cc];
            float m = warp_max(fmaxf(v0, v1));
            float s = warp_sum(expf(v0 - m) + expf(v1 - m));
            float lse = m + logf(s);
            la[l][cc] = v0 - lse;
            la[l + 32][cc] = v1 - lse;
        }
        __syncthreads();
    }
    for (int idx = tid; idx < 4096; idx += 1024) {
        int i = idx >> 6, j = idx & 63;
        la[i][j] = expf(la[i][j]);
    }
    __syncthreads();
    float local = 0.f;
    for (int idx = tid; idx < 8192; idx += 1024) {
        int i = idx >> 7, d = idx & 127;
        const float* ce = &g_em[(b * 128 + 64) * cD + d];
        float pc = 0.f;
#pragma unroll
        for (int j = 0; j < 64; j++) pc = fmaf(la[i][j], ce[j * cD], pc);
        float qv = g_em[(b * 128 + i) * cD + d];
        local += fmaxf(qv - pc, 0.f);
    }
    local = warp_sum(local);
    if (l == 0) red[w] = local;
    __syncthreads();
    if (tid == 0) {
        float tot = 0.f;
        for (int i = 0; i < 32; i++) tot += red[i];
        out[b] += -0.9f * tot;  // CW
    }
}

// ---------------- launch ----------------
extern "C" void kernel_launch(void* const* d_in, const int* in_sizes, int n_in,
                              void* d_out, int out_size) {
    const float* nf      = (const float*)d_in[0];
    const float* ef      = (const float*)d_in[1];
    const float* enc_nw  = (const float*)d_in[2];
    const float* enc_nb  = (const float*)d_in[3];
    const float* enc_ew  = (const float*)d_in[4];
    const float* enc_eb  = (const float*)d_in[5];
    const float* msg_w1  = (const float*)d_in[6];
    const float* msg_b1  = (const float*)d_in[7];
    const float* msg_w2  = (const float*)d_in[8];
    const float* msg_b2  = (const float*)d_in[9];
    const float* rmsg_w1 = (const float*)d_in[10];
    const float* rmsg_b1 = (const float*)d_in[11];
    const float* rmsg_w2 = (const float*)d_in[12];
    const float* rmsg_b2 = (const float*)d_in[13];
    const float* upd_w1  = (const float*)d_in[14];
    const float* upd_b1  = (const float*)d_in[15];
    const float* upd_w2  = (const float*)d_in[16];
    const float* upd_b2  = (const float*)d_in[17];
    const float* sk_w1   = (const float*)d_in[18];
    const float* sk_b1   = (const float*)d_in[19];
    const float* sk_w2   = (const float*)d_in[20];
    const float* sk_b2   = (const float*)d_in[21];
    const int* from_idx  = (const int*)d_in[22];
    const int* to_idx    = (const int*)d_in[23];
    const int* qs        = (const int*)d_in[24];
    const int* cs        = (const int*)d_in[25];
    float* out = (float*)d_out;

    // encode
    encode_kernel<<<cN, 128>>>(nf, enc_nw, enc_nb, 0);
    encode_kernel<<<cE, 128>>>(ef, enc_ew, enc_eb, 1);

    // 3 message-passing steps
    for (int step = 0; step < 3; step++) {
        zero_agg_kernel<<<(cN * cD + 1023) / 1024, 1024>>>();
        mlp_kernel<384, 0><<<cE / TM, 128>>>(from_idx, to_idx, msg_w1, msg_b1, msg_w2, msg_b2, to_idx, 0);
        mlp_kernel<384, 0><<<cE / TM, 128>>>(to_idx, from_idx, rmsg_w1, rmsg_b1, rmsg_w2, rmsg_b2, from_idx, 0);
        mlp_kernel<256, 1><<<cN / TM, 128>>>(nullptr, nullptr, upd_w1, upd_b1, upd_w2, upd_b2, nullptr, 3);
    }

    // final messages -> em = f + r
    mlp_kernel<384, 0><<<cE / TM, 128>>>(from_idx, to_idx, msg_w1, msg_b1, msg_w2, msg_b2, nullptr, 1);
    mlp_kernel<384, 0><<<cE / TM, 128>>>(to_idx, from_idx, rmsg_w1, rmsg_b1, rmsg_w2, rmsg_b2, nullptr, 2);

    // SK head, node plan, node align, edge (kron+sinkhorn+align)
    sk_kernel<<<cB * 2 * cMAXN / 4, 256>>>(sk_w1, sk_b1, sk_w2, sk_b2, qs, cs);
    node_plan_kernel<<<cB, 1024>>>();
    node_align_kernel<<<cB, 256>>>(out);
    edge_kernel<<<cB, 1024>>>(from_idx, to_idx, out);
}

// round 6
// speedup vs baseline: 1.9669x; 1.6320x over previous
#include <cuda_runtime.h>
#include <cuda_bf16.h>
#include <cstdint>

// ---------------- problem constants ----------------
constexpr int cB    = 256;
constexpr int cNPG  = 28;
constexpr int cMAXN = 32;
constexpr int cD    = 128;
constexpr int cN    = 2 * cB * cNPG;   // 14336 nodes
constexpr int cE    = 2 * cB * 64;     // 32768 edges

// ---------------- scratch (device globals) ----------------
__device__ float g_h[cN * cD];
__device__ float g_e[cE * cD];
__device__ float g_agg[cN * cD];
__device__ float g_em[cE * cD];
__device__ float g_tqc[cB * 2 * cMAXN * 64];
__device__ float g_plan[cB * cMAXN * cMAXN];

// weight scratch: per matrix, bf16 hi array [K][N] then bf16 lo array [K][N]
__device__ __align__(256) unsigned char g_wt[1441792];
constexpr size_t OFF_MSG1  = 0;          // 384x256: 393216
constexpr size_t OFF_RMSG1 = 393216;
constexpr size_t OFF_UPD1  = 786432;     // 256x256: 262144
constexpr size_t OFF_MSG2  = 1048576;    // 256x128: 131072
constexpr size_t OFF_RMSG2 = 1179648;
constexpr size_t OFF_UPD2  = 1310720;

// ---------------- smem layout for mlp_mma ----------------
// X: 64 rows x 392 cols bf16 (hi, lo)   (valid cols: K1<=384)
// W: 64 rows x 264 cols bf16 (hi, lo)   (stage1 chunk 64x256; stage2 uses stride 136)
// Hid aliases X region with stride 264
constexpr int X_HI  = 0;
constexpr int X_LO  = 50176;             // 64*392*2
constexpr int W_HI  = 100352;
constexpr int W_LO  = 134144;            // +64*264*2
constexpr int IDX_O = 167936;
constexpr int SMEM_MLP = 168704;
constexpr int XS  = 392;                 // X row stride (bf16 elems)
constexpr int HS  = 264;                 // hid / stage1-W row stride
constexpr int W2S = 136;                 // stage2 W row stride

// ---------------- PTX helpers (portable: ldmatrix + mma.sync) ----------------
__device__ __forceinline__ uint32_t smem_u32(const void* p) {
    uint32_t a;
    asm("{ .reg .u64 t; cvta.to.shared.u64 t, %1; cvt.u32.u64 %0, t; }" : "=r"(a) : "l"(p));
    return a;
}
__device__ __forceinline__ void ldsm_x4(uint32_t* r, uint32_t addr) {
    asm volatile("ldmatrix.sync.aligned.m8n8.x4.shared.b16 {%0,%1,%2,%3}, [%4];"
        : "=r"(r[0]), "=r"(r[1]), "=r"(r[2]), "=r"(r[3]) : "r"(addr));
}
__device__ __forceinline__ void ldsm_x2t(uint32_t* r, uint32_t addr) {
    asm volatile("ldmatrix.sync.aligned.m8n8.x2.trans.shared.b16 {%0,%1}, [%2];"
        : "=r"(r[0]), "=r"(r[1]) : "r"(addr));
}
__device__ __forceinline__ void mma16816(float* d, const uint32_t* a, const uint32_t* b) {
    asm volatile(
        "mma.sync.aligned.m16n8k16.row.col.f32.bf16.bf16.f32 "
        "{%0,%1,%2,%3}, {%4,%5,%6,%7}, {%8,%9}, {%0,%1,%2,%3};"
        : "+f"(d[0]), "+f"(d[1]), "+f"(d[2]), "+f"(d[3])
        : "r"(a[0]), "r"(a[1]), "r"(a[2]), "r"(a[3]), "r"(b[0]), "r"(b[1]));
}

// bf16 hi/lo split of two floats packed into u32s
__device__ __forceinline__ uint32_t bf16_split2(float x0, float x1, uint32_t& lo_out) {
    __nv_bfloat16 h0 = __float2bfloat16(x0);
    __nv_bfloat16 h1 = __float2bfloat16(x1);
    __nv_bfloat16 l0 = __float2bfloat16(x0 - __bfloat162float(h0));
    __nv_bfloat16 l1 = __float2bfloat16(x1 - __bfloat162float(h1));
    lo_out = (uint32_t)__bfloat16_as_ushort(l0) | ((uint32_t)__bfloat16_as_ushort(l1) << 16);
    return (uint32_t)__bfloat16_as_ushort(h0) | ((uint32_t)__bfloat16_as_ushort(h1) << 16);
}

// ---------------- warp helpers ----------------
__device__ __forceinline__ float warp_max(float v) {
#pragma unroll
    for (int o = 16; o > 0; o >>= 1) v = fmaxf(v, __shfl_xor_sync(0xffffffffu, v, o));
    return v;
}
__device__ __forceinline__ float warp_sum(float v) {
#pragma unroll
    for (int o = 16; o > 0; o >>= 1) v += __shfl_xor_sync(0xffffffffu, v, o);
    return v;
}

// ---------------- weight prep: fp32 [K][N] -> bf16 hi [K][N] + lo [K][N] ----------------
__global__ void prep_w(const float* __restrict__ W, unsigned char* __restrict__ dst, int KH) {
    int idx = blockIdx.x * blockDim.x + threadIdx.x;
    if (idx >= KH) return;
    float x = W[idx];
    __nv_bfloat16 hb = __float2bfloat16(x);
    __nv_bfloat16 lb = __float2bfloat16(x - __bfloat162float(hb));
    ((unsigned short*)dst)[idx]      = __bfloat16_as_ushort(hb);
    ((unsigned short*)dst)[KH + idx] = __bfloat16_as_ushort(lb);
}

// ---------------- encoders ----------------
__global__ void encode_kernel(const float* __restrict__ x, const float* __restrict__ W,
                              const float* __restrict__ bias, int which) {
    int r = blockIdx.x;
    int d = threadIdx.x;
    __shared__ float sx[32];
    if (d < 32) sx[d] = x[r * 32 + d];
    __syncthreads();
    float acc = bias[d];
#pragma unroll
    for (int k = 0; k < 32; k++) acc = fmaf(sx[k], W[k * cD + d], acc);
    if (which == 0) g_h[r * cD + d] = acc;
    else            g_e[r * cD + d] = acc;
}

__global__ void zero_agg_kernel() {
    int i = blockIdx.x * blockDim.x + threadIdx.x;
    if (i < cN * cD) g_agg[i] = 0.f;
}

// ---------------- fused 2-layer MLP via mma.sync (bf16 split, fp32 accum) ----------------
// 64 rows per CTA, 8 warps = 4 row-groups x 2 N-halves.
// GATHER==0: X = [h[ia], h[ib], e] (K1=384);  GATHER==1: X = [agg, h] (K1=256)
// mode: 0 atomicAdd g_agg via scat; 1 store g_em; 2 add g_em; 3 add g_h
template <int K1, int GATHER>
__global__ void __launch_bounds__(256) mlp_mma(
    const int* __restrict__ ia, const int* __restrict__ ib,
    const unsigned char* __restrict__ w1t, const float* __restrict__ b1p,
    const unsigned char* __restrict__ w2t, const float* __restrict__ b2p,
    const int* __restrict__ scat, int mode) {
    extern __shared__ __align__(16) unsigned char smem[];
    const int tid = threadIdx.x, lane = tid & 31, wid = tid >> 5;
    const int e0 = blockIdx.x * 64;
    int* sIa = (int*)(smem + IDX_O);
    int* sIb = sIa + 64;
    int* sSc = sIb + 64;
    if (tid < 64) {
        if (GATHER == 0) { sIa[tid] = ia[e0 + tid]; sIb[tid] = ib[e0 + tid]; }
        sSc[tid] = scat ? scat[e0 + tid] : 0;
    }
    __syncthreads();

    // ---- gather X -> bf16 hi/lo in smem ----
    if (GATHER == 0) {
        for (int i = tid; i < 6144; i += 256) {
            int r = i / 96, q = i - r * 96;
            int seg = q >> 5, c4 = (q & 31) << 2;
            const float* src = (seg == 0) ? g_h + (size_t)sIa[r] * cD + c4
                             : (seg == 1) ? g_h + (size_t)sIb[r] * cD + c4
                                          : g_e + (size_t)(e0 + r) * cD + c4;
            float4 v = *(const float4*)src;
            int col = seg * 128 + c4;
            uint32_t lo0, hi0 = bf16_split2(v.x, v.y, lo0);
            uint32_t lo1, hi1 = bf16_split2(v.z, v.w, lo1);
            uint32_t off = ((uint32_t)r * XS + col) * 2;
            *(uint32_t*)(smem + X_HI + off)     = hi0;
            *(uint32_t*)(smem + X_HI + off + 4) = hi1;
            *(uint32_t*)(smem + X_LO + off)     = lo0;
            *(uint32_t*)(smem + X_LO + off + 4) = lo1;
        }
    } else {
        for (int i = tid; i < 4096; i += 256) {
            int r = i >> 6, q = i & 63;
            int seg = q >> 5, c4 = (q & 31) << 2;
            const float* src = (seg == 0 ? g_agg : g_h) + (size_t)(e0 + r) * cD + c4;
            float4 v = *(const float4*)src;
            int col = seg * 128 + c4;
            uint32_t lo0, hi0 = bf16_split2(v.x, v.y, lo0);
            uint32_t lo1, hi1 = bf16_split2(v.z, v.w, lo1);
            uint32_t off = ((uint32_t)r * XS + col) * 2;
            *(uint32_t*)(smem + X_HI + off)     = hi0;
            *(uint32_t*)(smem + X_HI + off + 4) = hi1;
            *(uint32_t*)(smem + X_LO + off)     = lo0;
            *(uint32_t*)(smem + X_LO + off + 4) = lo1;
        }
    }

    const int rg = (wid & 3) << 4;          // row group base (16 rows)
    const int n0 = (wid >> 2) << 7;         // stage1 N-half base (128 cols)
    const int m_ = lane >> 3, r_ = lane & 7;
    const int arow = rg + ((m_ & 1) << 3) + r_;
    const int acol = (m_ >> 1) << 3;
    const uint32_t sb = smem_u32(smem);
    const uint32_t aHiB = sb + X_HI + ((uint32_t)arow * XS + acol) * 2;
    const uint32_t aLoB = sb + X_LO + ((uint32_t)arow * XS + acol) * 2;
    const int bRow = lane & 15;

    float acc[16][4];
#pragma unroll
    for (int j = 0; j < 16; j++)
#pragma unroll
        for (int q = 0; q < 4; q++) acc[j][q] = 0.f;

    // ---- stage 1: hidden = relu(X @ W1 + b1), K chunks of 64 ----
    constexpr int NCH = K1 / 64;
    for (int kc = 0; kc < NCH; kc++) {
        __syncthreads();
        {
            const float4* srch = (const float4*)(w1t + (size_t)kc * 32768);
            const float4* srcl = (const float4*)(w1t + (size_t)K1 * 512 + (size_t)kc * 32768);
            for (int i = tid; i < 2048; i += 256) {
                int rr = i >> 5, cc = i & 31;
                *(float4*)(smem + W_HI + rr * (HS * 2) + cc * 16) = srch[i];
                *(float4*)(smem + W_LO + rr * (HS * 2) + cc * 16) = srcl[i];
            }
        }
        __syncthreads();
#pragma unroll
        for (int kt = 0; kt < 4; kt++) {
            int kg = kc * 64 + kt * 16;
            uint32_t aHi[4], aLo[4];
            ldsm_x4(aHi, aHiB + kg * 2);
            ldsm_x4(aLo, aLoB + kg * 2);
            uint32_t bh_base = sb + W_HI + ((uint32_t)(kt * 16 + bRow) * HS + n0) * 2;
            uint32_t bl_base = sb + W_LO + ((uint32_t)(kt * 16 + bRow) * HS + n0) * 2;
#pragma unroll
            for (int j = 0; j < 16; j++) {
                uint32_t bh[2], bl[2];
                ldsm_x2t(bh, bh_base + j * 16);
                ldsm_x2t(bl, bl_base + j * 16);
                mma16816(acc[j], aHi, bh);
                mma16816(acc[j], aHi, bl);
                mma16816(acc[j], aLo, bh);
            }
        }
    }

    // ---- epilogue 1: bias + relu -> bf16 hi/lo hidden (aliases X region) ----
    __syncthreads();
    {
        int c = n0 + (lane & 3) * 2;
        int r1 = rg + (lane >> 2);
#pragma unroll
        for (int j = 0; j < 16; j++) {
            int cc = c + j * 8;
            float bb0 = __ldg(b1p + cc), bb1 = __ldg(b1p + cc + 1);
            float v00 = fmaxf(acc[j][0] + bb0, 0.f), v01 = fmaxf(acc[j][1] + bb1, 0.f);
            float v10 = fmaxf(acc[j][2] + bb0, 0.f), v11 = fmaxf(acc[j][3] + bb1, 0.f);
            uint32_t lo0, hi0 = bf16_split2(v00, v01, lo0);
            uint32_t lo1, hi1 = bf16_split2(v10, v11, lo1);
            *(uint32_t*)(smem + X_HI + ((uint32_t)r1 * HS + cc) * 2)       = hi0;
            *(uint32_t*)(smem + X_LO + ((uint32_t)r1 * HS + cc) * 2)       = lo0;
            *(uint32_t*)(smem + X_HI + ((uint32_t)(r1 + 8) * HS + cc) * 2) = hi1;
            *(uint32_t*)(smem + X_LO + ((uint32_t)(r1 + 8) * HS + cc) * 2) = lo1;
        }
    }

    // ---- stage 2: out = hidden @ W2 + b2, K=256 in chunks of 64 ----
    const int n2 = (wid >> 2) << 6;         // stage2 N-half base (64 cols)
    const uint32_t a2HiB = sb + X_HI + ((uint32_t)arow * HS + acol) * 2;
    const uint32_t a2LoB = sb + X_LO + ((uint32_t)arow * HS + acol) * 2;
    float acc2[8][4];
#pragma unroll
    for (int j = 0; j < 8; j++)
#pragma unroll
        for (int q = 0; q < 4; q++) acc2[j][q] = 0.f;

    for (int kc = 0; kc < 4; kc++) {
        __syncthreads();
        {
            const float4* srch = (const float4*)(w2t + (size_t)kc * 16384);
            const float4* srcl = (const float4*)(w2t + 65536 + (size_t)kc * 16384);
            for (int i = tid; i < 1024; i += 256) {
                int rr = i >> 4, cc = i & 15;
                *(float4*)(smem + W_HI + rr * (W2S * 2) + cc * 16) = srch[i];
                *(float4*)(smem + W_LO + rr * (W2S * 2) + cc * 16) = srcl[i];
            }
        }
        __syncthreads();
#pragma unroll
        for (int kt = 0; kt < 4; kt++) {
            int kg = kc * 64 + kt * 16;
            uint32_t aHi[4], aLo[4];
            ldsm_x4(aHi, a2HiB + kg * 2);
            ldsm_x4(aLo, a2LoB + kg * 2);
            uint32_t bh_base = sb + W_HI + ((uint32_t)(kt * 16 + bRow) * W2S + n2) * 2;
            uint32_t bl_base = sb + W_LO + ((uint32_t)(kt * 16 + bRow) * W2S + n2) * 2;
#pragma unroll
            for (int j = 0; j < 8; j++) {
                uint32_t bh[2], bl[2];
                ldsm_x2t(bh, bh_base + j * 16);
                ldsm_x2t(bl, bl_base + j * 16);
                mma16816(acc2[j], aHi, bh);
                mma16816(acc2[j], aHi, bl);
                mma16816(acc2[j], aLo, bh);
            }
        }
    }

    // ---- epilogue 2: bias + mode write ----
    {
        int c = n2 + (lane & 3) * 2;
        int r1 = rg + (lane >> 2);
#pragma unroll
        for (int j = 0; j < 8; j++) {
            int cc = c + j * 8;
            float bb0 = __ldg(b2p + cc), bb1 = __ldg(b2p + cc + 1);
            float v[2][2] = {{acc2[j][0] + bb0, acc2[j][1] + bb1},
                             {acc2[j][2] + bb0, acc2[j][3] + bb1}};
#pragma unroll
            for (int h = 0; h < 2; h++) {
                int r = r1 + h * 8;
                if (mode == 0) {
                    int nidx = sSc[r];
                    atomicAdd(&g_agg[(size_t)nidx * cD + cc], v[h][0]);
                    atomicAdd(&g_agg[(size_t)nidx * cD + cc + 1], v[h][1]);
                } else if (mode == 1) {
                    *(float2*)&g_em[(size_t)(e0 + r) * cD + cc] = make_float2(v[h][0], v[h][1]);
                } else if (mode == 2) {
                    g_em[(size_t)(e0 + r) * cD + cc]     += v[h][0];
                    g_em[(size_t)(e0 + r) * cD + cc + 1] += v[h][1];
                } else {
                    g_h[(size_t)(e0 + r) * cD + cc]     += v[h][0];
                    g_h[(size_t)(e0 + r) * cD + cc + 1] += v[h][1];
                }
            }
        }
    }
}

// ---------------- SK head ----------------
__global__ void __launch_bounds__(256) sk_kernel(
    const float* __restrict__ w1p, const float* __restrict__ b1p,
    const float* __restrict__ w2p, const float* __restrict__ b2p,
    const int* __restrict__ qs, const int* __restrict__ cs) {
    int t = threadIdx.x;
    int lr = t >> 6, j = t & 63;
    int row = blockIdx.x * 4 + lr;
    int b = row >> 6, sp = row & 63, s = sp >> 5, p = sp & 31;
    __shared__ float sx[4][128];
    __shared__ float sh[4][64];
    {
        bool valid = p < cNPG;
        int node = (b * 2 + s) * cNPG + p;
        sx[lr][j]      = valid ? g_h[node * cD + j]      : 0.f;
        sx[lr][j + 64] = valid ? g_h[node * cD + j + 64] : 0.f;
    }
    __syncthreads();
    float a = b1p[j];
#pragma unroll
    for (int k = 0; k < 128; k++) a = fmaf(sx[lr][k], w1p[k * 64 + j], a);
    sh[lr][j] = fmaxf(a, 0.f);
    __syncthreads();
    float o = b2p[j];
#pragma unroll
    for (int k = 0; k < 64; k++) o = fmaf(sh[lr][k], w2p[k * 64 + j], o);
    int size = (s == 0) ? qs[b] : cs[b];
    if (p >= size) o = 0.f;
    g_tqc[row * 64 + j] = o;
}

// ---------------- node scores + Sinkhorn ----------------
__global__ void __launch_bounds__(1024) node_plan_kernel() {
    int b = blockIdx.x;
    int tid = threadIdx.x;
    __shared__ float smq[32][65];
    __shared__ float smc[32][65];
    __shared__ float la[32 * 33];
    for (int idx = tid; idx < 2048; idx += 1024) {
        int r = idx >> 6, d = idx & 63;
        smq[r][d] = g_tqc[b * 4096 + idx];
        smc[r][d] = g_tqc[b * 4096 + 2048 + idx];
    }
    __syncthreads();
    int q = tid >> 5, c = tid & 31;
    float v = 0.f;
#pragma unroll
    for (int d = 0; d < 64; d++) v = fmaf(smq[q][d], smc[c][d], v);
    v *= 10.f;
    for (int it = 0; it < 20; it++) {
        float m = warp_max(v);
        float sum = warp_sum(expf(v - m));
        v -= m + logf(sum);
        la[q * 33 + c] = v;
        __syncthreads();
        float u = la[c * 33 + q];
        m = warp_max(u);
        sum = warp_sum(expf(u - m));
        u -= m + logf(sum);
        la[c * 33 + q] = u;
        __syncthreads();
        v = la[q * 33 + c];
    }
    g_plan[b * 1024 + q * 32 + c] = expf(v);
}

// ---------------- node alignment ----------------
__global__ void __launch_bounds__(256) node_align_kernel(float* __restrict__ out) {
    int b = blockIdx.x, tid = threadIdx.x;
    __shared__ float sp_[32 * 32];
    __shared__ float scn[32][128];
    __shared__ float red[8];
    for (int idx = tid; idx < 1024; idx += 256) sp_[idx] = g_plan[b * 1024 + idx];
    for (int idx = tid; idx < 4096; idx += 256) {
        int p = idx >> 7, d = idx & 127;
        scn[p][d] = (p < cNPG) ? g_h[((b * 2 + 1) * cNPG + p) * cD + d] : 0.f;
    }
    __syncthreads();
    float local = 0.f;
    for (int idx = tid; idx < 4096; idx += 256) {
        int q = idx >> 7, d = idx & 127;
        float pc = 0.f;
#pragma unroll
        for (int c = 0; c < 32; c++) pc = fmaf(sp_[q * 32 + c], scn[c][d], pc);
        float qv = (q < cNPG) ? g_h[((b * 2) * cNPG + q) * cD + d] : 0.f;
        local += fmaxf(qv - pc, 0.f);
    }
    local = warp_sum(local);
    if ((tid & 31) == 0) red[tid >> 5] = local;
    __syncthreads();
    if (tid == 0) {
        float tot = 0.f;
        for (int i = 0; i < 8; i++) tot += red[i];
        out[b] = -tot;
    }
}

// ---------------- edge kron + Sinkhorn + alignment ----------------
__global__ void __launch_bounds__(1024) edge_kernel(
    const int* __restrict__ from_idx, const int* __restrict__ to_idx,
    float* __restrict__ out) {
    int b = blockIdx.x, tid = threadIdx.x;
    __shared__ float T[32 * 32];
    __shared__ float la[64][65];
    __shared__ int qf[64], qt[64], cf[64], ct[64];
    __shared__ float red[32];

    T[tid & 1023] = g_plan[b * 1024 + (tid & 1023)];
    if (tid < 64) {
        qf[tid] = from_idx[b * 128 + tid] % cNPG;
        qt[tid] = to_idx[b * 128 + tid] % cNPG;
        cf[tid] = from_idx[b * 128 + 64 + tid] % cNPG;
        ct[tid] = to_idx[b * 128 + 64 + tid] % cNPG;
    }
    __syncthreads();
    for (int idx = tid; idx < 4096; idx += 1024) {
        int i = idx >> 6, j = idx & 63;
        float s = T[qf[i] * 32 + cf[j]] * T[qt[i] * 32 + ct[j]]
                + T[qf[i] * 32 + ct[j]] * T[qt[i] * 32 + cf[j]];
        la[i][j] = s * 10.f;
    }
    __syncthreads();
    int w = tid >> 5, l = tid & 31;
    for (int it = 0; it < 20; it++) {
#pragma unroll
        for (int rr_ = 0; rr_ < 2; rr_++) {
            int rr = w + rr_ * 32;
            float v0 = la[rr][l], v1 = la[rr][l + 32];
            float m = warp_max(fmaxf(v0, v1));
            float s = warp_sum(expf(v0 - m) + expf(v1 - m));
            float lse = m + logf(s);
            la[rr][l] = v0 - lse;
            la[rr][l + 32] = v1 - lse;
        }
        __syncthreads();
#pragma unroll
        for (int cc_ = 0; cc_ < 2; cc_++) {
            int cc = w + cc_ * 32;
            float v0 = la[l][cc], v1 = la[l + 32][cc];
            float m = warp_max(fmaxf(v0, v1));
            float s = warp_sum(expf(v0 - m) + expf(v1 - m));
            float lse = m + logf(s);
            la[l][cc] = v0 - lse;
            la[l + 32][cc] = v1 - lse;
        }
        __syncthreads();
    }
    for (int idx = tid; idx < 4096; idx += 1024) {
        int i = idx >> 6, j = idx & 63;
        la[i][j] = expf(la[i][j]);
    }
    __syncthreads();
    float local = 0.f;
    for (int idx = tid; idx < 8192; idx += 1024) {
        int i = idx >> 7, d = idx & 127;
        const float* ce = &g_em[(b * 128 + 64) * cD + d];
        float pc = 0.f;
#pragma unroll
        for (int j = 0; j < 64; j++) pc = fmaf(la[i][j], ce[j * cD], pc);
        float qv = g_em[(b * 128 + i) * cD + d];
        local += fmaxf(qv - pc, 0.f);
    }
    local = warp_sum(local);
    if (l == 0) red[w] = local;
    __syncthreads();
    if (tid == 0) {
        float tot = 0.f;
        for (int i = 0; i < 32; i++) tot += red[i];
        out[b] += -0.9f * tot;
    }
}

// ---------------- launch ----------------
extern "C" void kernel_launch(void* const* d_in, const int* in_sizes, int n_in,
                              void* d_out, int out_size) {
    const float* nf      = (const float*)d_in[0];
    const float* ef      = (const float*)d_in[1];
    const float* enc_nw  = (const float*)d_in[2];
    const float* enc_nb  = (const float*)d_in[3];
    const float* enc_ew  = (const float*)d_in[4];
    const float* enc_eb  = (const float*)d_in[5];
    const float* msg_w1  = (const float*)d_in[6];
    const float* msg_b1  = (const float*)d_in[7];
    const float* msg_w2  = (const float*)d_in[8];
    const float* msg_b2  = (const float*)d_in[9];
    const float* rmsg_w1 = (const float*)d_in[10];
    const float* rmsg_b1 = (const float*)d_in[11];
    const float* rmsg_w2 = (const float*)d_in[12];
    const float* rmsg_b2 = (const float*)d_in[13];
    const float* upd_w1  = (const float*)d_in[14];
    const float* upd_b1  = (const float*)d_in[15];
    const float* upd_w2  = (const float*)d_in[16];
    const float* upd_b2  = (const float*)d_in[17];
    const float* sk_w1   = (const float*)d_in[18];
    const float* sk_b1   = (const float*)d_in[19];
    const float* sk_w2   = (const float*)d_in[20];
    const float* sk_b2   = (const float*)d_in[21];
    const int* from_idx  = (const int*)d_in[22];
    const int* to_idx    = (const int*)d_in[23];
    const int* qs        = (const int*)d_in[24];
    const int* cs        = (const int*)d_in[25];
    float* out = (float*)d_out;

    unsigned char* wt = nullptr;
    cudaGetSymbolAddress((void**)&wt, g_wt);
    cudaFuncSetAttribute(mlp_mma<384, 0>, cudaFuncAttributeMaxDynamicSharedMemorySize, SMEM_MLP);
    cudaFuncSetAttribute(mlp_mma<256, 1>, cudaFuncAttributeMaxDynamicSharedMemorySize, SMEM_MLP);

    // weight prep (bf16 hi/lo split, layout preserved [K][N])
    prep_w<<<(384 * 256 + 255) / 256, 256>>>(msg_w1,  wt + OFF_MSG1,  384 * 256);
    prep_w<<<(384 * 256 + 255) / 256, 256>>>(rmsg_w1, wt + OFF_RMSG1, 384 * 256);
    prep_w<<<(256 * 256 + 255) / 256, 256>>>(upd_w1,  wt + OFF_UPD1,  256 * 256);
    prep_w<<<(256 * 128 + 255) / 256, 256>>>(msg_w2,  wt + OFF_MSG2,  256 * 128);
    prep_w<<<(256 * 128 + 255) / 256, 256>>>(rmsg_w2, wt + OFF_RMSG2, 256 * 128);
    prep_w<<<(256 * 128 + 255) / 256, 256>>>(upd_w2,  wt + OFF_UPD2,  256 * 128);

    // encode
    encode_kernel<<<cN, 128>>>(nf, enc_nw, enc_nb, 0);
    encode_kernel<<<cE, 128>>>(ef, enc_ew, enc_eb, 1);

    // 3 message-passing steps
    for (int step = 0; step < 3; step++) {
        zero_agg_kernel<<<(cN * cD + 1023) / 1024, 1024>>>();
        mlp_mma<384, 0><<<cE / 64, 256, SMEM_MLP>>>(from_idx, to_idx, wt + OFF_MSG1, msg_b1,
                                                    wt + OFF_MSG2, msg_b2, to_idx, 0);
        mlp_mma<384, 0><<<cE / 64, 256, SMEM_MLP>>>(to_idx, from_idx, wt + OFF_RMSG1, rmsg_b1,
                                                    wt + OFF_RMSG2, rmsg_b2, from_idx, 0);
        mlp_mma<256, 1><<<cN / 64, 256, SMEM_MLP>>>(nullptr, nullptr, wt + OFF_UPD1, upd_b1,
                                                    wt + OFF_UPD2, upd_b2, nullptr, 3);
    }

    // final messages -> em = f + r
    mlp_mma<384, 0><<<cE / 64, 256, SMEM_MLP>>>(from_idx, to_idx, wt + OFF_MSG1, msg_b1,
                                                wt + OFF_MSG2, msg_b2, nullptr, 1);
    mlp_mma<384, 0><<<cE / 64, 256, SMEM_MLP>>>(to_idx, from_idx, wt + OFF_RMSG1, rmsg_b1,
                                                wt + OFF_RMSG2, rmsg_b2, nullptr, 2);

    // SK head, node plan, node align, edge
    sk_kernel<<<cB * 2 * cMAXN / 4, 256>>>(sk_w1, sk_b1, sk_w2, sk_b2, qs, cs);
    node_plan_kernel<<<cB, 1024>>>();
    node_align_kernel<<<cB, 256>>>(out);
    edge_kernel<<<cB, 1024>>>(from_idx, to_idx, out);
}

// round 7
// speedup vs baseline: 2.2661x; 1.1521x over previous
#include <cuda_runtime.h>
#include <cuda_bf16.h>
#include <cstdint>

// ---------------- problem constants ----------------
constexpr int cB    = 256;
constexpr int cNPG  = 28;
constexpr int cMAXN = 32;
constexpr int cD    = 128;
constexpr int cN    = 2 * cB * cNPG;   // 14336 nodes
constexpr int cE    = 2 * cB * 64;     // 32768 edges

// ---------------- scratch (device globals) ----------------
__device__ float g_h[cN * cD];
__device__ float g_e[cE * cD];
__device__ float g_agg[cN * cD];
__device__ float g_em[cE * cD];
__device__ float g_tqc[cB * 2 * cMAXN * 64];
__device__ float g_plan[cB * cMAXN * cMAXN];

// weight scratch: per matrix, bf16 hi array [K][N] then bf16 lo array [K][N]
__device__ __align__(256) unsigned char g_wt[1441792];
constexpr size_t OFF_MSG1  = 0;          // 384x256
constexpr size_t OFF_RMSG1 = 393216;     // 384x256 (rows 0-127 <-> 128-255 swapped)
constexpr size_t OFF_UPD1  = 786432;     // 256x256
constexpr size_t OFF_MSG2  = 1048576;    // 256x128
constexpr size_t OFF_RMSG2 = 1179648;
constexpr size_t OFF_UPD2  = 1310720;

// ---------------- smem layouts ----------------
// edge kernel: X 64x392 hi/lo | W1 2 bufs (K=32, stride 264) -> hidden | W2 2 bufs | idx
constexpr int eX_HI = 0;
constexpr int eX_LO = 50176;             // 64*392*2
constexpr int eWB   = 100352;            // 2 x 33792 (also hidden hi @ +0, lo @ +33792)
constexpr int eW2B  = 167936;            // 2 x 17408
constexpr int eIDX  = 202752;
constexpr int SMEM_EDGE = 203264;
// upd kernel
constexpr int uX_HI = 0;
constexpr int uX_LO = 33792;             // 64*264*2
constexpr int uWB   = 67584;
constexpr int uW2B  = 135168;
constexpr int SMEM_UPD = 169984;

// ---------------- PTX helpers (portable) ----------------
__device__ __forceinline__ uint32_t smem_u32(const void* p) {
    uint32_t a;
    asm("{ .reg .u64 t; cvta.to.shared.u64 t, %1; cvt.u32.u64 %0, t; }" : "=r"(a) : "l"(p));
    return a;
}
__device__ __forceinline__ void ldsm_x4(uint32_t* r, uint32_t addr) {
    asm volatile("ldmatrix.sync.aligned.m8n8.x4.shared.b16 {%0,%1,%2,%3}, [%4];"
        : "=r"(r[0]), "=r"(r[1]), "=r"(r[2]), "=r"(r[3]) : "r"(addr));
}
__device__ __forceinline__ void ldsm_x4t(uint32_t* r, uint32_t addr) {
    asm volatile("ldmatrix.sync.aligned.m8n8.x4.trans.shared.b16 {%0,%1,%2,%3}, [%4];"
        : "=r"(r[0]), "=r"(r[1]), "=r"(r[2]), "=r"(r[3]) : "r"(addr));
}
__device__ __forceinline__ void mma16816(float* d, const uint32_t* a, const uint32_t* b) {
    asm volatile(
        "mma.sync.aligned.m16n8k16.row.col.f32.bf16.bf16.f32 "
        "{%0,%1,%2,%3}, {%4,%5,%6,%7}, {%8,%9}, {%0,%1,%2,%3};"
        : "+f"(d[0]), "+f"(d[1]), "+f"(d[2]), "+f"(d[3])
        : "r"(a[0]), "r"(a[1]), "r"(a[2]), "r"(a[3]), "r"(b[0]), "r"(b[1]));
}
__device__ __forceinline__ void cp16(uint32_t dst, const void* src) {
    asm volatile("cp.async.cg.shared.global [%0], [%1], 16;" :: "r"(dst), "l"(src));
}
#define CP_COMMIT() asm volatile("cp.async.commit_group;" ::: "memory")
#define CP_WAIT0()  asm volatile("cp.async.wait_group 0;" ::: "memory")
#define CP_WAIT1()  asm volatile("cp.async.wait_group 1;" ::: "memory")

__device__ __forceinline__ uint32_t bf16_split2(float x0, float x1, uint32_t& lo_out) {
    __nv_bfloat16 h0 = __float2bfloat16(x0);
    __nv_bfloat16 h1 = __float2bfloat16(x1);
    __nv_bfloat16 l0 = __float2bfloat16(x0 - __bfloat162float(h0));
    __nv_bfloat16 l1 = __float2bfloat16(x1 - __bfloat162float(h1));
    lo_out = (uint32_t)__bfloat16_as_ushort(l0) | ((uint32_t)__bfloat16_as_ushort(l1) << 16);
    return (uint32_t)__bfloat16_as_ushort(h0) | ((uint32_t)__bfloat16_as_ushort(h1) << 16);
}

__device__ __forceinline__ float warp_max(float v) {
#pragma unroll
    for (int o = 16; o > 0; o >>= 1) v = fmaxf(v, __shfl_xor_sync(0xffffffffu, v, o));
    return v;
}
__device__ __forceinline__ float warp_sum(float v) {
#pragma unroll
    for (int o = 16; o > 0; o >>= 1) v += __shfl_xor_sync(0xffffffffu, v, o);
    return v;
}

// ---------------- weight prep ----------------
// fp32 [K][H] -> bf16 hi [K][H] + lo [K][H]; optional swap of row blocks [0:128)<->[128:256)
__global__ void prep_w(const float* __restrict__ W, unsigned char* __restrict__ dst,
                       int K, int H, int swap) {
    int idx = blockIdx.x * blockDim.x + threadIdx.x;
    if (idx >= K * H) return;
    int k = idx / H, n = idx - k * H;
    float x = W[idx];
    __nv_bfloat16 hb = __float2bfloat16(x);
    __nv_bfloat16 lb = __float2bfloat16(x - __bfloat162float(hb));
    int kd = k;
    if (swap) kd = (k < 128) ? k + 128 : (k < 256 ? k - 128 : k);
    int o = kd * H + n;
    ((unsigned short*)dst)[o]         = __bfloat16_as_ushort(hb);
    ((unsigned short*)dst)[K * H + o] = __bfloat16_as_ushort(lb);
}

// ---------------- encoders ----------------
__global__ void encode_kernel(const float* __restrict__ x, const float* __restrict__ W,
                              const float* __restrict__ bias, int which) {
    int r = blockIdx.x;
    int d = threadIdx.x;
    __shared__ float sx[32];
    if (d < 32) sx[d] = x[r * 32 + d];
    __syncthreads();
    float acc = bias[d];
#pragma unroll
    for (int k = 0; k < 32; k++) acc = fmaf(sx[k], W[k * cD + d], acc);
    if (which == 0) g_h[r * cD + d] = acc;
    else            g_e[r * cD + d] = acc;
}

__global__ void zero_agg_kernel() {
    int i = blockIdx.x * blockDim.x + threadIdx.x;
    if (i < cN * cD) g_agg[i] = 0.f;
}

// ---------------- core: one fused 2-layer MLP (stage1 K1->256 relu, stage2 256->128) ----------------
// X already staged in smem (bf16 hi/lo, stride XST). Output accumulators in out[8][4] (no stage2 bias).
template <int K1, int XST, int XHI, int XLO, int WB, int W2B>
__device__ __forceinline__ void run_mlp(
    unsigned char* smem, uint32_t sb,
    const unsigned char* __restrict__ w1t, const float* __restrict__ b1p,
    const unsigned char* __restrict__ w2t,
    int tid, int lane, int wid, float out[8][4]) {
    const int rg = (wid & 3) << 4;
    const int n0 = (wid >> 2) << 7;
    const int n2 = (wid >> 2) << 6;
    const int m_ = lane >> 3, r_ = lane & 7;
    const int arow = rg + ((m_ & 1) << 3) + r_;
    const int acol = (m_ >> 1) << 3;
    const int bRow = lane & 15;
    const int bAdd = (lane >> 4) << 3;
    const uint32_t aHiB = sb + XHI + ((uint32_t)arow * XST + acol) * 2;
    const uint32_t aLoB = sb + XLO + ((uint32_t)arow * XST + acol) * 2;

    float acc[16][4];
#pragma unroll
    for (int j = 0; j < 16; j++)
#pragma unroll
        for (int q = 0; q < 4; q++) acc[j][q] = 0.f;

    constexpr int NC1 = K1 / 32;
    // prologue: issue W1 chunk 0
    for (int i = tid; i < 2048; i += 256) {
        int half = i >> 10, rr = (i >> 5) & 31, cc = i & 31;
        cp16(sb + WB + half * 16896 + rr * 528 + cc * 16,
             w1t + (size_t)half * (K1 * 512) + (size_t)rr * 512 + cc * 16);
    }
    CP_COMMIT();

    for (int c = 0; c < NC1; c++) {
        const int buf = c & 1;
        __syncthreads();                       // buffer reuse + (c==0) X-gather visibility
        if (c + 1 < NC1) {
            const int nb = (c + 1) & 1;
            for (int i = tid; i < 2048; i += 256) {
                int half = i >> 10, rr = (i >> 5) & 31, cc = i & 31;
                cp16(sb + WB + nb * 33792 + half * 16896 + rr * 528 + cc * 16,
                     w1t + (size_t)half * (K1 * 512) + (size_t)((c + 1) * 32 + rr) * 512 + cc * 16);
            }
            CP_COMMIT();
            CP_WAIT1();
        } else {
            CP_WAIT0();
        }
        __syncthreads();
        const uint32_t wb1 = sb + WB + buf * 33792;
#pragma unroll
        for (int kt = 0; kt < 2; kt++) {
            int kg = c * 32 + kt * 16;
            uint32_t aHi[4], aLo[4];
            ldsm_x4(aHi, aHiB + kg * 2);
            ldsm_x4(aLo, aLoB + kg * 2);
            uint32_t bb = wb1 + ((uint32_t)(kt * 16 + bRow) * 264 + n0 + bAdd) * 2;
#pragma unroll
            for (int j = 0; j < 8; j++) {
                uint32_t bh[4], bl[4];
                ldsm_x4t(bh, bb + j * 32);
                ldsm_x4t(bl, bb + 16896 + j * 32);
                mma16816(acc[2 * j],     aHi, bh);
                mma16816(acc[2 * j + 1], aHi, bh + 2);
                mma16816(acc[2 * j],     aHi, bl);
                mma16816(acc[2 * j + 1], aHi, bl + 2);
                mma16816(acc[2 * j],     aLo, bh);
                mma16816(acc[2 * j + 1], aLo, bh + 2);
            }
        }
    }

    // epilogue 1: bias + relu -> hidden (bf16 hi/lo) overwriting W1 staging
    __syncthreads();
    {
        int cb = n0 + (lane & 3) * 2;
        int r1 = rg + (lane >> 2);
#pragma unroll
        for (int j = 0; j < 16; j++) {
            int cc = cb + j * 8;
            float b0 = __ldg(b1p + cc), b1 = __ldg(b1p + cc + 1);
            float v00 = fmaxf(acc[j][0] + b0, 0.f), v01 = fmaxf(acc[j][1] + b1, 0.f);
            float v10 = fmaxf(acc[j][2] + b0, 0.f), v11 = fmaxf(acc[j][3] + b1, 0.f);
            uint32_t lo0, hi0 = bf16_split2(v00, v01, lo0);
            uint32_t lo1, hi1 = bf16_split2(v10, v11, lo1);
            *(uint32_t*)(smem + WB + ((uint32_t)r1 * 264 + cc) * 2)               = hi0;
            *(uint32_t*)(smem + WB + 33792 + ((uint32_t)r1 * 264 + cc) * 2)       = lo0;
            *(uint32_t*)(smem + WB + ((uint32_t)(r1 + 8) * 264 + cc) * 2)         = hi1;
            *(uint32_t*)(smem + WB + 33792 + ((uint32_t)(r1 + 8) * 264 + cc) * 2) = lo1;
        }
    }

    // stage 2: 8 chunks of K=32
    float acc2[8][4];
#pragma unroll
    for (int j = 0; j < 8; j++)
#pragma unroll
        for (int q = 0; q < 4; q++) acc2[j][q] = 0.f;
    const uint32_t a2HiB = sb + WB + ((uint32_t)arow * 264 + acol) * 2;
    const uint32_t a2LoB = sb + WB + 33792 + ((uint32_t)arow * 264 + acol) * 2;

    for (int i = tid; i < 1024; i += 256) {
        int half = i >> 9, rr = (i >> 4) & 31, cc = i & 15;
        cp16(sb + W2B + half * 8704 + rr * 272 + cc * 16,
             w2t + (size_t)half * 65536 + (size_t)rr * 256 + cc * 16);
    }
    CP_COMMIT();

    for (int c = 0; c < 8; c++) {
        const int buf = c & 1;
        __syncthreads();                       // hidden visibility (c==0) + buffer reuse
        if (c + 1 < 8) {
            const int nb = (c + 1) & 1;
            for (int i = tid; i < 1024; i += 256) {
                int half = i >> 9, rr = (i >> 4) & 31, cc = i & 15;
                cp16(sb + W2B + nb * 17408 + half * 8704 + rr * 272 + cc * 16,
                     w2t + (size_t)half * 65536 + (size_t)((c + 1) * 32 + rr) * 256 + cc * 16);
            }
            CP_COMMIT();
            CP_WAIT1();
        } else {
            CP_WAIT0();
        }
        __syncthreads();
        const uint32_t wb2 = sb + W2B + buf * 17408;
#pragma unroll
        for (int kt = 0; kt < 2; kt++) {
            int kg = c * 32 + kt * 16;
            uint32_t aHi[4], aLo[4];
            ldsm_x4(aHi, a2HiB + kg * 2);
            ldsm_x4(aLo, a2LoB + kg * 2);
            uint32_t bb = wb2 + ((uint32_t)(kt * 16 + bRow) * 136 + n2 + bAdd) * 2;
#pragma unroll
            for (int j = 0; j < 4; j++) {
                uint32_t bh[4], bl[4];
                ldsm_x4t(bh, bb + j * 32);
                ldsm_x4t(bl, bb + 8704 + j * 32);
                mma16816(acc2[2 * j],     aHi, bh);
                mma16816(acc2[2 * j + 1], aHi, bh + 2);
                mma16816(acc2[2 * j],     aHi, bl);
                mma16816(acc2[2 * j + 1], aHi, bl + 2);
                mma16816(acc2[2 * j],     aLo, bh);
                mma16816(acc2[2 * j + 1], aLo, bh + 2);
            }
        }
    }
    __syncthreads();                           // region safe for caller / next run
#pragma unroll
    for (int j = 0; j < 8; j++)
#pragma unroll
        for (int q = 0; q < 4; q++) out[j][q] = acc2[j][q];
}

// ---------------- edge kernel: fused msg + rmsg MLPs ----------------
// MODE 0: atomicAdd f->g_agg[to], r->g_agg[from];  MODE 1: g_em = f + r
template <int MODE>
__global__ void __launch_bounds__(256) edge_mlp(
    const int* __restrict__ from_idx, const int* __restrict__ to_idx,
    const unsigned char* __restrict__ wt,
    const float* __restrict__ b1m, const float* __restrict__ b2m,
    const float* __restrict__ b1r, const float* __restrict__ b2r) {
    extern __shared__ __align__(16) unsigned char smem[];
    const uint32_t sb = smem_u32(smem);
    const int tid = threadIdx.x, lane = tid & 31, wid = tid >> 5;
    const int e0 = blockIdx.x * 64;
    int* sF = (int*)(smem + eIDX);
    int* sT = sF + 64;
    if (tid < 64) { sF[tid] = from_idx[e0 + tid]; sT[tid] = to_idx[e0 + tid]; }
    __syncthreads();

    // gather X = [h[from], h[to], e] -> bf16 hi/lo (stride 392)
    for (int i = tid; i < 6144; i += 256) {
        int r = i / 96, q = i - r * 96;
        int seg = q >> 5, c4 = (q & 31) << 2;
        const float* src = (seg == 0) ? g_h + (size_t)sF[r] * cD + c4
                         : (seg == 1) ? g_h + (size_t)sT[r] * cD + c4
                                      : g_e + (size_t)(e0 + r) * cD + c4;
        float4 v = *(const float4*)src;
        int col = seg * 128 + c4;
        uint32_t lo0, hi0 = bf16_split2(v.x, v.y, lo0);
        uint32_t lo1, hi1 = bf16_split2(v.z, v.w, lo1);
        uint32_t off = ((uint32_t)r * 392 + col) * 2;
        *(uint32_t*)(smem + eX_HI + off)     = hi0;
        *(uint32_t*)(smem + eX_HI + off + 4) = hi1;
        *(uint32_t*)(smem + eX_LO + off)     = lo0;
        *(uint32_t*)(smem + eX_LO + off + 4) = lo1;
    }

    float facc[8][4], racc[8][4];
    run_mlp<384, 392, eX_HI, eX_LO, eWB, eW2B>(smem, sb, wt + OFF_MSG1, b1m,
                                               wt + OFF_MSG2, tid, lane, wid, facc);
    run_mlp<384, 392, eX_HI, eX_LO, eWB, eW2B>(smem, sb, wt + OFF_RMSG1, b1r,
                                               wt + OFF_RMSG2, tid, lane, wid, racc);

    // final epilogue
    const int rg = (wid & 3) << 4;
    const int n2 = (wid >> 2) << 6;
    const int cb = n2 + (lane & 3) * 2;
    const int r1 = rg + (lane >> 2);
#pragma unroll
    for (int j = 0; j < 8; j++) {
        int cc = cb + j * 8;
        float fb0 = __ldg(b2m + cc), fb1 = __ldg(b2m + cc + 1);
        float rb0 = __ldg(b2r + cc), rb1 = __ldg(b2r + cc + 1);
        float f00 = facc[j][0] + fb0, f01 = facc[j][1] + fb1;
        float f10 = facc[j][2] + fb0, f11 = facc[j][3] + fb1;
        float r00 = racc[j][0] + rb0, r01 = racc[j][1] + rb1;
        float r10 = racc[j][2] + rb0, r11 = racc[j][3] + rb1;
        if (MODE == 0) {
            int tA = sT[r1], tB = sT[r1 + 8];
            int fA = sF[r1], fB = sF[r1 + 8];
            atomicAdd(&g_agg[(size_t)tA * cD + cc],     f00);
            atomicAdd(&g_agg[(size_t)tA * cD + cc + 1], f01);
            atomicAdd(&g_agg[(size_t)tB * cD + cc],     f10);
            atomicAdd(&g_agg[(size_t)tB * cD + cc + 1], f11);
            atomicAdd(&g_agg[(size_t)fA * cD + cc],     r00);
            atomicAdd(&g_agg[(size_t)fA * cD + cc + 1], r01);
            atomicAdd(&g_agg[(size_t)fB * cD + cc],     r10);
            atomicAdd(&g_agg[(size_t)fB * cD + cc + 1], r11);
        } else {
            *(float2*)&g_em[(size_t)(e0 + r1) * cD + cc]     = make_float2(f00 + r00, f01 + r01);
            *(float2*)&g_em[(size_t)(e0 + r1 + 8) * cD + cc] = make_float2(f10 + r10, f11 + r11);
        }
    }
}

// ---------------- upd kernel: h += mlp([agg, h]) ----------------
__global__ void __launch_bounds__(256) upd_mlp(
    const unsigned char* __restrict__ wt,
    const float* __restrict__ b1p, const float* __restrict__ b2p) {
    extern __shared__ __align__(16) unsigned char smem[];
    const uint32_t sb = smem_u32(smem);
    const int tid = threadIdx.x, lane = tid & 31, wid = tid >> 5;
    const int e0 = blockIdx.x * 64;

    for (int i = tid; i < 4096; i += 256) {
        int r = i >> 6, q = i & 63;
        int seg = q >> 5, c4 = (q & 31) << 2;
        const float* src = (seg == 0 ? g_agg : g_h) + (size_t)(e0 + r) * cD + c4;
        float4 v = *(const float4*)src;
        int col = seg * 128 + c4;
        uint32_t lo0, hi0 = bf16_split2(v.x, v.y, lo0);
        uint32_t lo1, hi1 = bf16_split2(v.z, v.w, lo1);
        uint32_t off = ((uint32_t)r * 264 + col) * 2;
        *(uint32_t*)(smem + uX_HI + off)     = hi0;
        *(uint32_t*)(smem + uX_HI + off + 4) = hi1;
        *(uint32_t*)(smem + uX_LO + off)     = lo0;
        *(uint32_t*)(smem + uX_LO + off + 4) = lo1;
    }

    float oacc[8][4];
    run_mlp<256, 264, uX_HI, uX_LO, uWB, uW2B>(smem, sb, wt + OFF_UPD1, b1p,
                                               wt + OFF_UPD2, tid, lane, wid, oacc);

    const int rg = (wid & 3) << 4;
    const int n2 = (wid >> 2) << 6;
    const int cb = n2 + (lane & 3) * 2;
    const int r1 = rg + (lane >> 2);
#pragma unroll
    for (int j = 0; j < 8; j++) {
        int cc = cb + j * 8;
        float b0 = __ldg(b2p + cc), b1 = __ldg(b2p + cc + 1);
        g_h[(size_t)(e0 + r1) * cD + cc]         += oacc[j][0] + b0;
        g_h[(size_t)(e0 + r1) * cD + cc + 1]     += oacc[j][1] + b1;
        g_h[(size_t)(e0 + r1 + 8) * cD + cc]     += oacc[j][2] + b0;
        g_h[(size_t)(e0 + r1 + 8) * cD + cc + 1] += oacc[j][3] + b1;
    }
}

// ---------------- SK head ----------------
__global__ void __launch_bounds__(256) sk_kernel(
    const float* __restrict__ w1p, const float* __restrict__ b1p,
    const float* __restrict__ w2p, const float* __restrict__ b2p,
    const int* __restrict__ qs, const int* __restrict__ cs) {
    int t = threadIdx.x;
    int lr = t >> 6, j = t & 63;
    int row = blockIdx.x * 4 + lr;
    int b = row >> 6, sp = row & 63, s = sp >> 5, p = sp & 31;
    __shared__ float sx[4][128];
    __shared__ float sh[4][64];
    {
        bool valid = p < cNPG;
        int node = (b * 2 + s) * cNPG + p;
        sx[lr][j]      = valid ? g_h[node * cD + j]      : 0.f;
        sx[lr][j + 64] = valid ? g_h[node * cD + j + 64] : 0.f;
    }
    __syncthreads();
    float a = b1p[j];
#pragma unroll
    for (int k = 0; k < 128; k++) a = fmaf(sx[lr][k], w1p[k * 64 + j], a);
    sh[lr][j] = fmaxf(a, 0.f);
    __syncthreads();
    float o = b2p[j];
#pragma unroll
    for (int k = 0; k < 64; k++) o = fmaf(sh[lr][k], w2p[k * 64 + j], o);
    int size = (s == 0) ? qs[b] : cs[b];
    if (p >= size) o = 0.f;
    g_tqc[row * 64 + j] = o;
}

// ---------------- node scores + Sinkhorn ----------------
__global__ void __launch_bounds__(1024) node_plan_kernel() {
    int b = blockIdx.x;
    int tid = threadIdx.x;
    __shared__ float smq[32][65];
    __shared__ float smc[32][65];
    __shared__ float la[32 * 33];
    for (int idx = tid; idx < 2048; idx += 1024) {
        int r = idx >> 6, d = idx & 63;
        smq[r][d] = g_tqc[b * 4096 + idx];
        smc[r][d] = g_tqc[b * 4096 + 2048 + idx];
    }
    __syncthreads();
    int q = tid >> 5, c = tid & 31;
    float v = 0.f;
#pragma unroll
    for (int d = 0; d < 64; d++) v = fmaf(smq[q][d], smc[c][d], v);
    v *= 10.f;
    for (int it = 0; it < 20; it++) {
        float m = warp_max(v);
        float sum = warp_sum(expf(v - m));
        v -= m + logf(sum);
        la[q * 33 + c] = v;
        __syncthreads();
        float u = la[c * 33 + q];
        m = warp_max(u);
        sum = warp_sum(expf(u - m));
        u -= m + logf(sum);
        la[c * 33 + q] = u;
        __syncthreads();
        v = la[q * 33 + c];
    }
    g_plan[b * 1024 + q * 32 + c] = expf(v);
}

// ---------------- node alignment ----------------
__global__ void __launch_bounds__(256) node_align_kernel(float* __restrict__ out) {
    int b = blockIdx.x, tid = threadIdx.x;
    __shared__ float sp_[32 * 32];
    __shared__ float scn[32][128];
    __shared__ float red[8];
    for (int idx = tid; idx < 1024; idx += 256) sp_[idx] = g_plan[b * 1024 + idx];
    for (int idx = tid; idx < 4096; idx += 256) {
        int p = idx >> 7, d = idx & 127;
        scn[p][d] = (p < cNPG) ? g_h[((b * 2 + 1) * cNPG + p) * cD + d] : 0.f;
    }
    __syncthreads();
    float local = 0.f;
    for (int idx = tid; idx < 4096; idx += 256) {
        int q = idx >> 7, d = idx & 127;
        float pc = 0.f;
#pragma unroll
        for (int c = 0; c < 32; c++) pc = fmaf(sp_[q * 32 + c], scn[c][d], pc);
        float qv = (q < cNPG) ? g_h[((b * 2) * cNPG + q) * cD + d] : 0.f;
        local += fmaxf(qv - pc, 0.f);
    }
    local = warp_sum(local);
    if ((tid & 31) == 0) red[tid >> 5] = local;
    __syncthreads();
    if (tid == 0) {
        float tot = 0.f;
        for (int i = 0; i < 8; i++) tot += red[i];
        out[b] = -tot;
    }
}

// ---------------- edge kron + Sinkhorn + alignment ----------------
__global__ void __launch_bounds__(1024) edge_align_kernel(
    const int* __restrict__ from_idx, const int* __restrict__ to_idx,
    float* __restrict__ out) {
    int b = blockIdx.x, tid = threadIdx.x;
    __shared__ float T[32 * 32];
    __shared__ float la[64][65];
    __shared__ int qf[64], qt[64], cf[64], ct[64];
    __shared__ float red[32];

    T[tid & 1023] = g_plan[b * 1024 + (tid & 1023)];
    if (tid < 64) {
        qf[tid] = from_idx[b * 128 + tid] % cNPG;
        qt[tid] = to_idx[b * 128 + tid] % cNPG;
        cf[tid] = from_idx[b * 128 + 64 + tid] % cNPG;
        ct[tid] = to_idx[b * 128 + 64 + tid] % cNPG;
    }
    __syncthreads();
    for (int idx = tid; idx < 4096; idx += 1024) {
        int i = idx >> 6, j = idx & 63;
        float s = T[qf[i] * 32 + cf[j]] * T[qt[i] * 32 + ct[j]]
                + T[qf[i] * 32 + ct[j]] * T[qt[i] * 32 + cf[j]];
        la[i][j] = s * 10.f;
    }
    __syncthreads();
    int w = tid >> 5, l = tid & 31;
    for (int it = 0; it < 20; it++) {
#pragma unroll
        for (int rr_ = 0; rr_ < 2; rr_++) {
            int rr = w + rr_ * 32;
            float v0 = la[rr][l], v1 = la[rr][l + 32];
            float m = warp_max(fmaxf(v0, v1));
            float s = warp_sum(expf(v0 - m) + expf(v1 - m));
            float lse = m + logf(s);
            la[rr][l] = v0 - lse;
            la[rr][l + 32] = v1 - lse;
        }
        __syncthreads();
#pragma unroll
        for (int cc_ = 0; cc_ < 2; cc_++) {
            int cc = w + cc_ * 32;
            float v0 = la[l][cc], v1 = la[l + 32][cc];
            float m = warp_max(fmaxf(v0, v1));
            float s = warp_sum(expf(v0 - m) + expf(v1 - m));
            float lse = m + logf(s);
            la[l][cc] = v0 - lse;
            la[l + 32][cc] = v1 - lse;
        }
        __syncthreads();
    }
    for (int idx = tid; idx < 4096; idx += 1024) {
        int i = idx >> 6, j = idx & 63;
        la[i][j] = expf(la[i][j]);
    }
    __syncthreads();
    float local = 0.f;
    for (int idx = tid; idx < 8192; idx += 1024) {
        int i = idx >> 7, d = idx & 127;
        const float* ce = &g_em[(b * 128 + 64) * cD + d];
        float pc = 0.f;
#pragma unroll
        for (int j = 0; j < 64; j++) pc = fmaf(la[i][j], ce[j * cD], pc);
        float qv = g_em[(b * 128 + i) * cD + d];
        local += fmaxf(qv - pc, 0.f);
    }
    local = warp_sum(local);
    if (l == 0) red[w] = local;
    __syncthreads();
    if (tid == 0) {
        float tot = 0.f;
        for (int i = 0; i < 32; i++) tot += red[i];
        out[b] += -0.9f * tot;
    }
}

// ---------------- launch ----------------
extern "C" void kernel_launch(void* const* d_in, const int* in_sizes, int n_in,
                              void* d_out, int out_size) {
    const float* nf      = (const float*)d_in[0];
    const float* ef      = (const float*)d_in[1];
    const float* enc_nw  = (const float*)d_in[2];
    const float* enc_nb  = (const float*)d_in[3];
    const float* enc_ew  = (const float*)d_in[4];
    const float* enc_eb  = (const float*)d_in[5];
    const float* msg_w1  = (const float*)d_in[6];
    const float* msg_b1  = (const float*)d_in[7];
    const float* msg_w2  = (const float*)d_in[8];
    const float* msg_b2  = (const float*)d_in[9];
    const float* rmsg_w1 = (const float*)d_in[10];
    const float* rmsg_b1 = (const float*)d_in[11];
    const float* rmsg_w2 = (const float*)d_in[12];
    const float* rmsg_b2 = (const float*)d_in[13];
    const float* upd_w1  = (const float*)d_in[14];
    const float* upd_b1  = (const float*)d_in[15];
    const float* upd_w2  = (const float*)d_in[16];
    const float* upd_b2  = (const float*)d_in[17];
    const float* sk_w1   = (const float*)d_in[18];
    const float* sk_b1   = (const float*)d_in[19];
    const float* sk_w2   = (const float*)d_in[20];
    const float* sk_b2   = (const float*)d_in[21];
    const int* from_idx  = (const int*)d_in[22];
    const int* to_idx    = (const int*)d_in[23];
    const int* qs        = (const int*)d_in[24];
    const int* cs        = (const int*)d_in[25];
    float* out = (float*)d_out;

    unsigned char* wt = nullptr;
    cudaGetSymbolAddress((void**)&wt, g_wt);
    cudaFuncSetAttribute(edge_mlp<0>, cudaFuncAttributeMaxDynamicSharedMemorySize, SMEM_EDGE);
    cudaFuncSetAttribute(edge_mlp<1>, cudaFuncAttributeMaxDynamicSharedMemorySize, SMEM_EDGE);
    cudaFuncSetAttribute(upd_mlp,     cudaFuncAttributeMaxDynamicSharedMemorySize, SMEM_UPD);

    // weight prep (bf16 hi/lo split; rmsg_w1 gets its first 256 rows block-swapped)
    prep_w<<<(384 * 256 + 255) / 256, 256>>>(msg_w1,  wt + OFF_MSG1,  384, 256, 0);
    prep_w<<<(384 * 256 + 255) / 256, 256>>>(rmsg_w1, wt + OFF_RMSG1, 384, 256, 1);
    prep_w<<<(256 * 256 + 255) / 256, 256>>>(upd_w1,  wt + OFF_UPD1,  256, 256, 0);
    prep_w<<<(256 * 128 + 255) / 256, 256>>>(msg_w2,  wt + OFF_MSG2,  256, 128, 0);
    prep_w<<<(256 * 128 + 255) / 256, 256>>>(rmsg_w2, wt + OFF_RMSG2, 256, 128, 0);
    prep_w<<<(256 * 128 + 255) / 256, 256>>>(upd_w2,  wt + OFF_UPD2,  256, 128, 0);

    // encode
    encode_kernel<<<cN, 128>>>(nf, enc_nw, enc_nb, 0);
    encode_kernel<<<cE, 128>>>(ef, enc_ew, enc_eb, 1);

    // 3 message-passing steps (msg+rmsg fused per call)
    for (int step = 0; step < 3; step++) {
        zero_agg_kernel<<<(cN * cD + 1023) / 1024, 1024>>>();
        edge_mlp<0><<<cE / 64, 256, SMEM_EDGE>>>(from_idx, to_idx, wt,
                                                 msg_b1, msg_b2, rmsg_b1, rmsg_b2);
        upd_mlp<<<cN / 64, 256, SMEM_UPD>>>(wt, upd_b1, upd_b2);
    }

    // final messages -> em = f + r (single fused call)
    edge_mlp<1><<<cE / 64, 256, SMEM_EDGE>>>(from_idx, to_idx, wt,
                                             msg_b1, msg_b2, rmsg_b1, rmsg_b2);

    // SK head, node plan, node align, edge align
    sk_kernel<<<cB * 2 * cMAXN / 4, 256>>>(sk_w1, sk_b1, sk_w2, sk_b2, qs, cs);
    node_plan_kernel<<<cB, 1024>>>();
    node_align_kernel<<<cB, 256>>>(out);
    edge_align_kernel<<<cB, 1024>>>(from_idx, to_idx, out);
}

// round 9
// speedup vs baseline: 3.1377x; 1.3847x over previous
#include <cuda_runtime.h>
#include <cuda_bf16.h>
#include <cstdint>

// ---------------- problem constants ----------------
constexpr int cB    = 256;
constexpr int cNPG  = 28;
constexpr int cMAXN = 32;
constexpr int cD    = 128;
constexpr int cN    = 2 * cB * cNPG;   // 14336 nodes
constexpr int cE    = 2 * cB * 64;     // 32768 edges

// ---------------- scratch (device globals) ----------------
__device__ float g_h[cN * cD];
__device__ float g_e[cE * cD];
__device__ float g_agg[cN * cD];
__device__ float g_em[cE * cD];
__device__ float g_tqc[cB * 2 * cMAXN * 64];
__device__ float g_plan[cB * cMAXN * cMAXN];

// weight scratch: per matrix, bf16 hi array [K][H] then bf16 lo array [K][H]
__device__ __align__(256) unsigned char g_wt[1441792];
constexpr size_t OFF_MSG1  = 0;          // 384x256
constexpr size_t OFF_RMSG1 = 393216;     // 384x256 (rows 0-127 <-> 128-255 swapped)
constexpr size_t OFF_UPD1  = 786432;     // 256x256
constexpr size_t OFF_MSG2  = 1048576;    // 256x128
constexpr size_t OFF_RMSG2 = 1179648;
constexpr size_t OFF_UPD2  = 1310720;

// ---------------- smem layouts (32-row tiles, XOR-swizzled, no padding) ----------------
// edge: X 32x384 hi/lo | W1 2x32768 (hidden 32768 + W2 2x16384 alias) | idx
constexpr int eX_HI = 0;                 // 24576
constexpr int eX_LO = 24576;             // 24576
constexpr int eWB   = 49152;             // W1 bufs at +0,+32768; hidden at +0 after stage1
constexpr int eW2B  = 81920;             // W2 bufs at +0,+16384
constexpr int eIDX  = 114688;
constexpr int SMEM_EDGE = 115200;
// upd: X 32x256 hi/lo
constexpr int uX_HI = 0;                 // 16384
constexpr int uX_LO = 16384;             // 16384
constexpr int uWB   = 32768;
constexpr int uW2B  = 65536;
constexpr int SMEM_UPD = 98304;

// ---------------- PTX helpers (portable) ----------------
__device__ __forceinline__ uint32_t smem_u32(const void* p) {
    uint32_t a;
    asm("{ .reg .u64 t; cvta.to.shared.u64 t, %1; cvt.u32.u64 %0, t; }" : "=r"(a) : "l"(p));
    return a;
}
__device__ __forceinline__ void ldsm_x4(uint32_t* r, uint32_t addr) {
    asm volatile("ldmatrix.sync.aligned.m8n8.x4.shared.b16 {%0,%1,%2,%3}, [%4];"
        : "=r"(r[0]), "=r"(r[1]), "=r"(r[2]), "=r"(r[3]) : "r"(addr));
}
__device__ __forceinline__ void ldsm_x4t(uint32_t* r, uint32_t addr) {
    asm volatile("ldmatrix.sync.aligned.m8n8.x4.trans.shared.b16 {%0,%1,%2,%3}, [%4];"
        : "=r"(r[0]), "=r"(r[1]), "=r"(r[2]), "=r"(r[3]) : "r"(addr));
}
__device__ __forceinline__ void mma16816(float* d, const uint32_t* a, const uint32_t* b) {
    asm volatile(
        "mma.sync.aligned.m16n8k16.row.col.f32.bf16.bf16.f32 "
        "{%0,%1,%2,%3}, {%4,%5,%6,%7}, {%8,%9}, {%0,%1,%2,%3};"
        : "+f"(d[0]), "+f"(d[1]), "+f"(d[2]), "+f"(d[3])
        : "r"(a[0]), "r"(a[1]), "r"(a[2]), "r"(a[3]), "r"(b[0]), "r"(b[1]));
}
__device__ __forceinline__ void cp16(uint32_t dst, const void* src) {
    asm volatile("cp.async.cg.shared.global [%0], [%1], 16;" :: "r"(dst), "l"(src));
}
#define CP_COMMIT() asm volatile("cp.async.commit_group;" ::: "memory")
#define CP_WAIT0()  asm volatile("cp.async.wait_group 0;" ::: "memory")

__device__ __forceinline__ uint32_t bf16_split2(float x0, float x1, uint32_t& lo_out) {
    __nv_bfloat16 h0 = __float2bfloat16(x0);
    __nv_bfloat16 h1 = __float2bfloat16(x1);
    __nv_bfloat16 l0 = __float2bfloat16(x0 - __bfloat162float(h0));
    __nv_bfloat16 l1 = __float2bfloat16(x1 - __bfloat162float(h1));
    lo_out = (uint32_t)__bfloat16_as_ushort(l0) | ((uint32_t)__bfloat16_as_ushort(l1) << 16);
    return (uint32_t)__bfloat16_as_ushort(h0) | ((uint32_t)__bfloat16_as_ushort(h1) << 16);
}

__device__ __forceinline__ float warp_max(float v) {
#pragma unroll
    for (int o = 16; o > 0; o >>= 1) v = fmaxf(v, __shfl_xor_sync(0xffffffffu, v, o));
    return v;
}
__device__ __forceinline__ float warp_sum(float v) {
#pragma unroll
    for (int o = 16; o > 0; o >>= 1) v += __shfl_xor_sync(0xffffffffu, v, o);
    return v;
}

// ---------------- fused weight prep (single launch) ----------------
__global__ void prep_all(const float* __restrict__ m1, const float* __restrict__ r1w,
                         const float* __restrict__ u1, const float* __restrict__ m2,
                         const float* __restrict__ r2w, const float* __restrict__ u2,
                         unsigned char* __restrict__ wt) {
    int idx = blockIdx.x * 256 + threadIdx.x;
    const float* src; size_t off; int K, H, swp, l;
    if      (idx < 98304)  { src = m1;  off = OFF_MSG1;  K = 384; H = 256; swp = 0; l = idx; }
    else if (idx < 196608) { src = r1w; off = OFF_RMSG1; K = 384; H = 256; swp = 1; l = idx - 98304; }
    else if (idx < 262144) { src = u1;  off = OFF_UPD1;  K = 256; H = 256; swp = 0; l = idx - 196608; }
    else if (idx < 294912) { src = m2;  off = OFF_MSG2;  K = 256; H = 128; swp = 0; l = idx - 262144; }
    else if (idx < 327680) { src = r2w; off = OFF_RMSG2; K = 256; H = 128; swp = 0; l = idx - 294912; }
    else if (idx < 360448) { src = u2;  off = OFF_UPD2;  K = 256; H = 128; swp = 0; l = idx - 327680; }
    else return;
    int k = l / H, n = l - k * H;
    float x = src[l];
    __nv_bfloat16 hb = __float2bfloat16(x);
    __nv_bfloat16 lb = __float2bfloat16(x - __bfloat162float(hb));
    int kd = k;
    if (swp) kd = (k < 128) ? k + 128 : (k < 256 ? k - 128 : k);
    int o = kd * H + n;
    unsigned short* d = (unsigned short*)(wt + off);
    d[o]         = __bfloat16_as_ushort(hb);
    d[K * H + o] = __bfloat16_as_ushort(lb);
}

// ---------------- encoder: 16 rows per block ----------------
__global__ void __launch_bounds__(128) encode16(const float* __restrict__ x,
                                                const float* __restrict__ W,
                                                const float* __restrict__ bias, int which) {
    __shared__ float sW[32 * 128];
    __shared__ float sx[16][32];
    int tid = threadIdx.x;
    int r0 = blockIdx.x * 16;
    for (int i = tid; i < 4096; i += 128) sW[i] = W[i];
    for (int i = tid; i < 512; i += 128) sx[i >> 5][i & 31] = x[r0 * 32 + i];
    __syncthreads();
    float b = bias[tid];
    float* dst = (which == 0) ? g_h : g_e;
#pragma unroll 4
    for (int rr = 0; rr < 16; rr++) {
        float acc = b;
#pragma unroll
        for (int k = 0; k < 32; k++) acc = fmaf(sx[rr][k], sW[k * 128 + tid], acc);
        dst[(size_t)(r0 + rr) * 128 + tid] = acc;
    }
}

__global__ void zero_agg_kernel() {
    int i = blockIdx.x * blockDim.x + threadIdx.x;
    if (i < cN * cD) g_agg[i] = 0.f;
}

// ---------------- core: one fused 2-layer MLP, 32 rows, XOR swizzle ----------------
// X staged in smem (bf16 hi/lo, stride XST bytes, swizzled). Output acc in out[4][4].
template <int K1, int XST, int XHI, int XLO, int WB, int W2B>
__device__ __forceinline__ void run_mlp(
    unsigned char* smem, uint32_t sb,
    const unsigned char* __restrict__ w1t, const float* __restrict__ b1p,
    const unsigned char* __restrict__ w2t,
    int tid, int lane, int wid, float out[4][4]) {
    const int rg = (wid & 1) << 4;          // 2 rowgroups of 16
    const int n0 = (wid >> 1) << 6;         // stage1: 4 colgroups of 64
    const int n2 = (wid >> 1) << 5;         // stage2: 4 colgroups of 32
    const int m_ = lane >> 3, r_ = lane & 7;
    const int arow = rg + ((m_ & 1) << 3) + r_;
    const int acol = (m_ >> 1) << 3;
    const int bRow = lane & 15;
    const int bAdd = (lane >> 4) << 3;
    const uint32_t aswz = (uint32_t)(arow & 7) << 4;
    const uint32_t aHiB = sb + XHI + (uint32_t)arow * XST;
    const uint32_t aLoB = sb + XLO + (uint32_t)arow * XST;
    const uint32_t bswz = (uint32_t)(bRow & 7) << 4;

    float acc[8][4];
#pragma unroll
    for (int j = 0; j < 8; j++)
#pragma unroll
        for (int q = 0; q < 4; q++) acc[j][q] = 0.f;

    constexpr int NC1 = K1 / 32;
    // prologue: W1 chunk 0 (hi 16384 + lo 16384 per buffer, swizzled)
    for (int i = tid; i < 2048; i += 256) {
        int comp = i >> 10, rr = (i >> 5) & 31, cc = i & 31;
        cp16(sb + WB + comp * 16384 + rr * 512 + ((cc * 16) ^ ((rr & 7) << 4)),
             w1t + (size_t)comp * (K1 * 512) + (size_t)rr * 512 + cc * 16);
    }
    CP_COMMIT();

    for (int c = 0; c < NC1; c++) {
        CP_WAIT0();
        __syncthreads();
        if (c + 1 < NC1) {
            const int nb = (c + 1) & 1;
            for (int i = tid; i < 2048; i += 256) {
                int comp = i >> 10, rr = (i >> 5) & 31, cc = i & 31;
                cp16(sb + WB + nb * 32768 + comp * 16384 + rr * 512 + ((cc * 16) ^ ((rr & 7) << 4)),
                     w1t + (size_t)comp * (K1 * 512) + (size_t)((c + 1) * 32 + rr) * 512 + cc * 16);
            }
            CP_COMMIT();
        }
        const uint32_t wb1 = sb + WB + (c & 1) * 32768;
#pragma unroll
        for (int kt = 0; kt < 2; kt++) {
            int kg = c * 32 + kt * 16;
            uint32_t aHi[4], aLo[4];
            uint32_t ac = ((uint32_t)((acol + kg) * 2)) ^ aswz;
            ldsm_x4(aHi, aHiB + ac);
            ldsm_x4(aLo, aLoB + ac);
            uint32_t bb = wb1 + (uint32_t)(kt * 16 + bRow) * 512;
#pragma unroll
            for (int j = 0; j < 4; j++) {
                uint32_t cbyte = ((uint32_t)((n0 + bAdd + j * 16) * 2)) ^ bswz;
                uint32_t bh[4], bl[4];
                ldsm_x4t(bh, bb + cbyte);
                ldsm_x4t(bl, bb + 16384 + cbyte);
                mma16816(acc[2 * j],     aHi, bh);
                mma16816(acc[2 * j + 1], aHi, bh + 2);
                mma16816(acc[2 * j],     aHi, bl);
                mma16816(acc[2 * j + 1], aHi, bl + 2);
                mma16816(acc[2 * j],     aLo, bh);
                mma16816(acc[2 * j + 1], aLo, bh + 2);
            }
        }
    }
    __syncthreads();

    // epilogue 1: bias + relu -> hidden (bf16 hi/lo) in WB (stride 512B, swizzled)
    {
        int cb = n0 + (lane & 3) * 2;
        int r1 = rg + (lane >> 2);
        uint32_t s1 = (uint32_t)(r1 & 7) << 4;
#pragma unroll
        for (int j = 0; j < 8; j++) {
            int cc = cb + j * 8;
            float b0 = __ldg(b1p + cc), b1v = __ldg(b1p + cc + 1);
            float v00 = fmaxf(acc[j][0] + b0, 0.f), v01 = fmaxf(acc[j][1] + b1v, 0.f);
            float v10 = fmaxf(acc[j][2] + b0, 0.f), v11 = fmaxf(acc[j][3] + b1v, 0.f);
            uint32_t lo0, hi0 = bf16_split2(v00, v01, lo0);
            uint32_t lo1, hi1 = bf16_split2(v10, v11, lo1);
            uint32_t o1 = ((uint32_t)(cc * 2)) ^ s1;
            *(uint32_t*)(smem + WB + r1 * 512 + o1)               = hi0;
            *(uint32_t*)(smem + WB + 16384 + r1 * 512 + o1)       = lo0;
            *(uint32_t*)(smem + WB + (r1 + 8) * 512 + o1)         = hi1;
            *(uint32_t*)(smem + WB + 16384 + (r1 + 8) * 512 + o1) = lo1;
        }
    }

    // stage 2: 8 chunks of K=32 (W2 buf = hi 8192 + lo 8192)
    float acc2[4][4];
#pragma unroll
    for (int j = 0; j < 4; j++)
#pragma unroll
        for (int q = 0; q < 4; q++) acc2[j][q] = 0.f;
    const uint32_t a2HiB = sb + WB + (uint32_t)arow * 512;
    const uint32_t a2LoB = a2HiB + 16384;

    for (int i = tid; i < 1024; i += 256) {
        int comp = i >> 9, rr = (i >> 4) & 31, cc = i & 15;
        cp16(sb + W2B + comp * 8192 + rr * 256 + ((cc * 16) ^ ((rr & 7) << 4)),
             w2t + (size_t)comp * 65536 + (size_t)rr * 256 + cc * 16);
    }
    CP_COMMIT();

    for (int c = 0; c < 8; c++) {
        CP_WAIT0();
        __syncthreads();
        if (c + 1 < 8) {
            const int nb = (c + 1) & 1;
            for (int i = tid; i < 1024; i += 256) {
                int comp = i >> 9, rr = (i >> 4) & 31, cc = i & 15;
                cp16(sb + W2B + nb * 16384 + comp * 8192 + rr * 256 + ((cc * 16) ^ ((rr & 7) << 4)),
                     w2t + (size_t)comp * 65536 + (size_t)((c + 1) * 32 + rr) * 256 + cc * 16);
            }
            CP_COMMIT();
        }
        const uint32_t wb2 = sb + W2B + (c & 1) * 16384;
#pragma unroll
        for (int kt = 0; kt < 2; kt++) {
            int kg = c * 32 + kt * 16;
            uint32_t aHi[4], aLo[4];
            uint32_t ac = ((uint32_t)((acol + kg) * 2)) ^ aswz;
            ldsm_x4(aHi, a2HiB + ac);
            ldsm_x4(aLo, a2LoB + ac);
            uint32_t bb = wb2 + (uint32_t)(kt * 16 + bRow) * 256;
#pragma unroll
            for (int j = 0; j < 2; j++) {
                uint32_t cbyte = ((uint32_t)((n2 + bAdd + j * 16) * 2)) ^ bswz;
                uint32_t bh[4], bl[4];
                ldsm_x4t(bh, bb + cbyte);
                ldsm_x4t(bl, bb + 8192 + cbyte);
                mma16816(acc2[2 * j],     aHi, bh);
                mma16816(acc2[2 * j + 1], aHi, bh + 2);
                mma16816(acc2[2 * j],     aHi, bl);
                mma16816(acc2[2 * j + 1], aHi, bl + 2);
                mma16816(acc2[2 * j],     aLo, bh);
                mma16816(acc2[2 * j + 1], aLo, bh + 2);
            }
        }
    }
    __syncthreads();
#pragma unroll
    for (int j = 0; j < 4; j++)
#pragma unroll
        for (int q = 0; q < 4; q++) out[j][q] = acc2[j][q];
}

// ---------------- edge kernel: fused msg + rmsg ----------------
template <int MODE>
__global__ void __launch_bounds__(256, 2) edge_mlp(
    const int* __restrict__ from_idx, const int* __restrict__ to_idx,
    const unsigned char* __restrict__ wt,
    const float* __restrict__ b1m, const float* __restrict__ b2m,
    const float* __restrict__ b1r, const float* __restrict__ b2r) {
    extern __shared__ __align__(16) unsigned char smem[];
    const uint32_t sb = smem_u32(smem);
    const int tid = threadIdx.x, lane = tid & 31, wid = tid >> 5;
    const int e0 = blockIdx.x * 32;
    int* sF = (int*)(smem + eIDX);
    int* sT = sF + 32;
    if (tid < 32) { sF[tid] = from_idx[e0 + tid]; sT[tid] = to_idx[e0 + tid]; }
    __syncthreads();

    // gather X = [h[from], h[to], e] -> bf16 hi/lo, swizzled (stride 768B)
    for (int i = tid; i < 3072; i += 256) {
        int r = i / 96, q = i - r * 96;
        int seg = q >> 5, c4 = (q & 31) << 2;
        const float* src = (seg == 0) ? g_h + (size_t)sF[r] * cD + c4
                         : (seg == 1) ? g_h + (size_t)sT[r] * cD + c4
                                      : g_e + (size_t)(e0 + r) * cD + c4;
        float4 v = *(const float4*)src;
        int col = seg * 128 + c4;
        uint32_t lo0, hi0 = bf16_split2(v.x, v.y, lo0);
        uint32_t lo1, hi1 = bf16_split2(v.z, v.w, lo1);
        uint32_t o = (uint32_t)r * 768 + (((uint32_t)(col * 2)) ^ ((uint32_t)(r & 7) << 4));
        *(uint32_t*)(smem + eX_HI + o)     = hi0;
        *(uint32_t*)(smem + eX_HI + o + 4) = hi1;
        *(uint32_t*)(smem + eX_LO + o)     = lo0;
        *(uint32_t*)(smem + eX_LO + o + 4) = lo1;
    }

    float facc[4][4], racc[4][4];
    run_mlp<384, 768, eX_HI, eX_LO, eWB, eW2B>(smem, sb, wt + OFF_MSG1, b1m,
                                               wt + OFF_MSG2, tid, lane, wid, facc);
    run_mlp<384, 768, eX_HI, eX_LO, eWB, eW2B>(smem, sb, wt + OFF_RMSG1, b1r,
                                               wt + OFF_RMSG2, tid, lane, wid, racc);

    const int rg = (wid & 1) << 4;
    const int n2 = (wid >> 1) << 5;
    const int cb = n2 + (lane & 3) * 2;
    const int r1 = rg + (lane >> 2);
#pragma unroll
    for (int j = 0; j < 4; j++) {
        int cc = cb + j * 8;
        float fb0 = __ldg(b2m + cc), fb1 = __ldg(b2m + cc + 1);
        float rb0 = __ldg(b2r + cc), rb1 = __ldg(b2r + cc + 1);
        float f00 = facc[j][0] + fb0, f01 = facc[j][1] + fb1;
        float f10 = facc[j][2] + fb0, f11 = facc[j][3] + fb1;
        float r00 = racc[j][0] + rb0, r01 = racc[j][1] + rb1;
        float r10 = racc[j][2] + rb0, r11 = racc[j][3] + rb1;
        if (MODE == 0) {
            int tA = sT[r1], tB = sT[r1 + 8];
            int fA = sF[r1], fB = sF[r1 + 8];
            atomicAdd(&g_agg[(size_t)tA * cD + cc],     f00);
            atomicAdd(&g_agg[(size_t)tA * cD + cc + 1], f01);
            atomicAdd(&g_agg[(size_t)tB * cD + cc],     f10);
            atomicAdd(&g_agg[(size_t)tB * cD + cc + 1], f11);
            atomicAdd(&g_agg[(size_t)fA * cD + cc],     r00);
            atomicAdd(&g_agg[(size_t)fA * cD + cc + 1], r01);
            atomicAdd(&g_agg[(size_t)fB * cD + cc],     r10);
            atomicAdd(&g_agg[(size_t)fB * cD + cc + 1], r11);
        } else {
            *(float2*)&g_em[(size_t)(e0 + r1) * cD + cc]     = make_float2(f00 + r00, f01 + r01);
            *(float2*)&g_em[(size_t)(e0 + r1 + 8) * cD + cc] = make_float2(f10 + r10, f11 + r11);
        }
    }
}

// ---------------- upd kernel: h += mlp([agg, h]) ----------------
__global__ void __launch_bounds__(256, 2) upd_mlp(
    const unsigned char* __restrict__ wt,
    const float* __restrict__ b1p, const float* __restrict__ b2p) {
    extern __shared__ __align__(16) unsigned char smem[];
    const uint32_t sb = smem_u32(smem);
    const int tid = threadIdx.x, lane = tid & 31, wid = tid >> 5;
    const int e0 = blockIdx.x * 32;

    for (int i = tid; i < 2048; i += 256) {
        int r = i >> 6, q = i & 63;
        int seg = q >> 5, c4 = (q & 31) << 2;
        const float* src = (seg == 0 ? g_agg : g_h) + (size_t)(e0 + r) * cD + c4;
        float4 v = *(const float4*)src;
        int col = seg * 128 + c4;
        uint32_t lo0, hi0 = bf16_split2(v.x, v.y, lo0);
        uint32_t lo1, hi1 = bf16_split2(v.z, v.w, lo1);
        uint32_t o = (uint32_t)r * 512 + (((uint32_t)(col * 2)) ^ ((uint32_t)(r & 7) << 4));
        *(uint32_t*)(smem + uX_HI + o)     = hi0;
        *(uint32_t*)(smem + uX_HI + o + 4) = hi1;
        *(uint32_t*)(smem + uX_LO + o)     = lo0;
        *(uint32_t*)(smem + uX_LO + o + 4) = lo1;
    }

    float oacc[4][4];
    run_mlp<256, 512, uX_HI, uX_LO, uWB, uW2B>(smem, sb, wt + OFF_UPD1, b1p,
                                               wt + OFF_UPD2, tid, lane, wid, oacc);

    const int rg = (wid & 1) << 4;
    const int n2 = (wid >> 1) << 5;
    const int cb = n2 + (lane & 3) * 2;
    const int r1 = rg + (lane >> 2);
#pragma unroll
    for (int j = 0; j < 4; j++) {
        int cc = cb + j * 8;
        float b0 = __ldg(b2p + cc), b1v = __ldg(b2p + cc + 1);
        g_h[(size_t)(e0 + r1) * cD + cc]         += oacc[j][0] + b0;
        g_h[(size_t)(e0 + r1) * cD + cc + 1]     += oacc[j][1] + b1v;
        g_h[(size_t)(e0 + r1 + 8) * cD + cc]     += oacc[j][2] + b0;
        g_h[(size_t)(e0 + r1 + 8) * cD + cc + 1] += oacc[j][3] + b1v;
    }
}

// ---------------- SK head ----------------
__global__ void __launch_bounds__(256) sk_kernel(
    const float* __restrict__ w1p, const float* __restrict__ b1p,
    const float* __restrict__ w2p, const float* __restrict__ b2p,
    const int* __restrict__ qs, const int* __restrict__ cs) {
    int t = threadIdx.x;
    int lr = t >> 6, j = t & 63;
    int row = blockIdx.x * 4 + lr;
    int b = row >> 6, sp = row & 63, s = sp >> 5, p = sp & 31;
    __shared__ float sx[4][128];
    __shared__ float sh[4][64];
    {
        bool valid = p < cNPG;
        int node = (b * 2 + s) * cNPG + p;
        sx[lr][j]      = valid ? g_h[node * cD + j]      : 0.f;
        sx[lr][j + 64] = valid ? g_h[node * cD + j + 64] : 0.f;
    }
    __syncthreads();
    float a = b1p[j];
#pragma unroll
    for (int k = 0; k < 128; k++) a = fmaf(sx[lr][k], w1p[k * 64 + j], a);
    sh[lr][j] = fmaxf(a, 0.f);
    __syncthreads();
    float o = b2p[j];
#pragma unroll
    for (int k = 0; k < 64; k++) o = fmaf(sh[lr][k], w2p[k * 64 + j], o);
    int size = (s == 0) ? qs[b] : cs[b];
    if (p >= size) o = 0.f;
    g_tqc[row * 64 + j] = o;
}

// ---------------- node scores + Sinkhorn (fast math) ----------------
__global__ void __launch_bounds__(1024) node_plan_kernel() {
    int b = blockIdx.x;
    int tid = threadIdx.x;
    __shared__ float smq[32][65];
    __shared__ float smc[32][65];
    __shared__ float la[32 * 33];
    for (int idx = tid; idx < 2048; idx += 1024) {
        int r = idx >> 6, d = idx & 63;
        smq[r][d] = g_tqc[b * 4096 + idx];
        smc[r][d] = g_tqc[b * 4096 + 2048 + idx];
    }
    __syncthreads();
    int q = tid >> 5, c = tid & 31;
    float v = 0.f;
#pragma unroll
    for (int d = 0; d < 64; d++) v = fmaf(smq[q][d], smc[c][d], v);
    v *= 10.f;
    // iteration 0 row pass needs max (raw scores can be large)
    {
        float m = warp_max(v);
        float sum = warp_sum(__expf(v - m));
        v -= m + __logf(sum);
        la[q * 33 + c] = v;
        __syncthreads();
        float u = la[c * 33 + q];             // <= 0 now
        float s = warp_sum(__expf(u));
        u -= __logf(s);
        la[c * 33 + q] = u;
        __syncthreads();
        v = la[q * 33 + c];
    }
    for (int it = 1; it < 20; it++) {
        float s = warp_sum(__expf(v));
        v -= __logf(s);
        la[q * 33 + c] = v;
        __syncthreads();
        float u = la[c * 33 + q];
        s = warp_sum(__expf(u));
        u -= __logf(s);
        la[c * 33 + q] = u;
        __syncthreads();
        v = la[q * 33 + c];
    }
    g_plan[b * 1024 + q * 32 + c] = __expf(v);
}

// ---------------- node alignment ----------------
__global__ void __launch_bounds__(256) node_align_kernel(float* __restrict__ out) {
    int b = blockIdx.x, tid = threadIdx.x;
    __shared__ float sp_[32 * 32];
    __shared__ float scn[32][128];
    __shared__ float red[8];
    for (int idx = tid; idx < 1024; idx += 256) sp_[idx] = g_plan[b * 1024 + idx];
    for (int idx = tid; idx < 4096; idx += 256) {
        int p = idx >> 7, d = idx & 127;
        scn[p][d] = (p < cNPG) ? g_h[((b * 2 + 1) * cNPG + p) * cD + d] : 0.f;
    }
    __syncthreads();
    float local = 0.f;
    for (int idx = tid; idx < 4096; idx += 256) {
        int q = idx >> 7, d = idx & 127;
        float pc = 0.f;
#pragma unroll
        for (int c = 0; c < 32; c++) pc = fmaf(sp_[q * 32 + c], scn[c][d], pc);
        float qv = (q < cNPG) ? g_h[((b * 2) * cNPG + q) * cD + d] : 0.f;
        local += fmaxf(qv - pc, 0.f);
    }
    local = warp_sum(local);
    if ((tid & 31) == 0) red[tid >> 5] = local;
    __syncthreads();
    if (tid == 0) {
        float tot = 0.f;
        for (int i = 0; i < 8; i++) tot += red[i];
        out[b] = -tot;
    }
}

// ---------------- edge kron + Sinkhorn + alignment (fast math, no max needed) ----------------
__global__ void __launch_bounds__(1024) edge_align_kernel(
    const int* __restrict__ from_idx, const int* __restrict__ to_idx,
    float* __restrict__ out) {
    int b = blockIdx.x, tid = threadIdx.x;
    __shared__ float T[32 * 32];
    __shared__ float la[64][65];
    __shared__ int qf[64], qt[64], cf[64], ct[64];
    __shared__ float red[32];

    T[tid & 1023] = g_plan[b * 1024 + (tid & 1023)];
    if (tid < 64) {
        qf[tid] = from_idx[b * 128 + tid] % cNPG;
        qt[tid] = to_idx[b * 128 + tid] % cNPG;
        cf[tid] = from_idx[b * 128 + 64 + tid] % cNPG;
        ct[tid] = to_idx[b * 128 + 64 + tid] % cNPG;
    }
    __syncthreads();
    // scores in [0, 20] -> exp safe without max subtraction throughout
    for (int idx = tid; idx < 4096; idx += 1024) {
        int i = idx >> 6, j = idx & 63;
        float s = T[qf[i] * 32 + cf[j]] * T[qt[i] * 32 + ct[j]]
                + T[qf[i] * 32 + ct[j]] * T[qt[i] * 32 + cf[j]];
        la[i][j] = s * 10.f;
    }
    __syncthreads();
    int w = tid >> 5, l = tid & 31;
    for (int it = 0; it < 20; it++) {
#pragma unroll
        for (int rr_ = 0; rr_ < 2; rr_++) {
            int rr = w + rr_ * 32;
            float v0 = la[rr][l], v1 = la[rr][l + 32];
            float s = warp_sum(__expf(v0) + __expf(v1));
            float lse = __logf(s);
            la[rr][l] = v0 - lse;
            la[rr][l + 32] = v1 - lse;
        }
        __syncthreads();
#pragma unroll
        for (int cc_ = 0; cc_ < 2; cc_++) {
            int cc = w + cc_ * 32;
            float v0 = la[l][cc], v1 = la[l + 32][cc];
            float s = warp_sum(__expf(v0) + __expf(v1));
            float lse = __logf(s);
            la[l][cc] = v0 - lse;
            la[l + 32][cc] = v1 - lse;
        }
        __syncthreads();
    }
    for (int idx = tid; idx < 4096; idx += 1024) {
        int i = idx >> 6, j = idx & 63;
        la[i][j] = __expf(la[i][j]);
    }
    __syncthreads();
    float local = 0.f;
    for (int idx = tid; idx < 8192; idx += 1024) {
        int i = idx >> 7, d = idx & 127;
        const float* ce = &g_em[(b * 128 + 64) * cD + d];
        float pc = 0.f;
#pragma unroll
        for (int j = 0; j < 64; j++) pc = fmaf(la[i][j], ce[j * cD], pc);
        float qv = g_em[(b * 128 + i) * cD + d];
        local += fmaxf(qv - pc, 0.f);
    }
    local = warp_sum(local);
    if (l == 0) red[w] = local;
    __syncthreads();
    if (tid == 0) {
        float tot = 0.f;
        for (int i = 0; i < 32; i++) tot += red[i];
        out[b] += -0.9f * tot;
    }
}

// ---------------- launch ----------------
extern "C" void kernel_launch(void* const* d_in, const int* in_sizes, int n_in,
                              void* d_out, int out_size) {
    const float* nf      = (const float*)d_in[0];
    const float* ef      = (const float*)d_in[1];
    const float* enc_nw  = (const float*)d_in[2];
    const float* enc_nb  = (const float*)d_in[3];
    const float* enc_ew  = (const float*)d_in[4];
    const float* enc_eb  = (const float*)d_in[5];
    const float* msg_w1  = (const float*)d_in[6];
    const float* msg_b1  = (const float*)d_in[7];
    const float* msg_w2  = (const float*)d_in[8];
    const float* msg_b2  = (const float*)d_in[9];
    const float* rmsg_w1 = (const float*)d_in[10];
    const float* rmsg_b1 = (const float*)d_in[11];
    const float* rmsg_w2 = (const float*)d_in[12];
    const float* rmsg_b2 = (const float*)d_in[13];
    const float* upd_w1  = (const float*)d_in[14];
    const float* upd_b1  = (const float*)d_in[15];
    const float* upd_w2  = (const float*)d_in[16];
    const float* upd_b2  = (const float*)d_in[17];
    const float* sk_w1   = (const float*)d_in[18];
    const float* sk_b1   = (const float*)d_in[19];
    const float* sk_w2   = (const float*)d_in[20];
    const float* sk_b2   = (const float*)d_in[21];
    const int* from_idx  = (const int*)d_in[22];
    const int* to_idx    = (const int*)d_in[23];
    const int* qs        = (const int*)d_in[24];
    const int* cs        = (const int*)d_in[25];
    float* out = (float*)d_out;

    unsigned char* wt = nullptr;
    cudaGetSymbolAddress((void**)&wt, g_wt);
    cudaFuncSetAttribute(edge_mlp<0>, cudaFuncAttributeMaxDynamicSharedMemorySize, SMEM_EDGE);
    cudaFuncSetAttribute(edge_mlp<1>, cudaFuncAttributeMaxDynamicSharedMemorySize, SMEM_EDGE);
    cudaFuncSetAttribute(upd_mlp,     cudaFuncAttributeMaxDynamicSharedMemorySize, SMEM_UPD);

    // weight prep (single fused launch)
    prep_all<<<1408, 256>>>(msg_w1, rmsg_w1, upd_w1, msg_w2, rmsg_w2, upd_w2, wt);

    // encode
    encode16<<<cN / 16, 128>>>(nf, enc_nw, enc_nb, 0);
    encode16<<<cE / 16, 128>>>(ef, enc_ew, enc_eb, 1);

    // 3 message-passing steps (msg+rmsg fused per call)
    for (int step = 0; step < 3; step++) {
        zero_agg_kernel<<<(cN * cD + 1023) / 1024, 1024>>>();
        edge_mlp<0><<<cE / 32, 256, SMEM_EDGE>>>(from_idx, to_idx, wt,
                                                 msg_b1, msg_b2, rmsg_b1, rmsg_b2);
        upd_mlp<<<cN / 32, 256, SMEM_UPD>>>(wt, upd_b1, upd_b2);
    }

    // final messages -> em = f + r
    edge_mlp<1><<<cE / 32, 256, SMEM_EDGE>>>(from_idx, to_idx, wt,
                                             msg_b1, msg_b2, rmsg_b1, rmsg_b2);

    // SK head, node plan, node align, edge align
    sk_kernel<<<cB * 2 * cMAXN / 4, 256>>>(sk_w1, sk_b1, sk_w2, sk_b2, qs, cs);
    node_plan_kernel<<<cB, 1024>>>();
    node_align_kernel<<<cB, 256>>>(out);
    edge_align_kernel<<<cB, 1024>>>(from_idx, to_idx, out);
}

// round 10
// speedup vs baseline: 3.2882x; 1.0480x over previous
#include <cuda_runtime.h>
#include <cuda_bf16.h>
#include <cstdint>

// ---------------- problem constants ----------------
constexpr int cB    = 256;
constexpr int cNPG  = 28;
constexpr int cMAXN = 32;
constexpr int cD    = 128;
constexpr int cN    = 2 * cB * cNPG;   // 14336 nodes
constexpr int cE    = 2 * cB * 64;     // 32768 edges

// ---------------- scratch (device globals) ----------------
__device__ float g_h[cN * cD];
__device__ float g_e[cE * cD];
__device__ float g_agg[cN * cD];
__device__ float g_em[cE * cD];
__device__ float g_tqc[cB * 2 * cMAXN * 64];
__device__ float g_plan[cB * cMAXN * cMAXN];
__device__ float g_pre[cN * 1024];     // [h@W1a | h@W1b | h@R1a | h@R1b]
__device__ float g_epre[cE * 512];     // [e@W1c + b1m | e@R1c + b1r]

// weight scratch (bf16 hi then lo per matrix)
__device__ __align__(256) unsigned char g_wt[1441792];
constexpr size_t OFF_UPD1  = 0;        // 256x256 : 262144 B
constexpr size_t OFF_MSG2  = 262144;   // 256x128 : 131072 B
constexpr size_t OFF_RMSG2 = 393216;
constexpr size_t OFF_UPD2  = 524288;
constexpr size_t OFF_WCAT  = 655360;   // 128x1024: 524288 B
constexpr size_t OFF_WEC   = 1179648;  // 128x512 : 262144 B

// ---------------- smem layouts ----------------
// pre_gemm: X hi 8K | X lo 8K | W bufs 2x32K
constexpr int SMEM_PRE = 81920;
// edge2: H hi 16K | H lo 16K | W2 bufs 2x16K | idx
constexpr int e2W2B = 32768;
constexpr int e2IDX = 65536;
constexpr int SMEM_EDGE2 = 65792;
// upd (unchanged R8)
constexpr int uX_HI = 0;
constexpr int uX_LO = 16384;
constexpr int uWB   = 32768;
constexpr int uW2B  = 65536;
constexpr int SMEM_UPD = 98304;

// ---------------- PTX helpers (portable) ----------------
__device__ __forceinline__ uint32_t smem_u32(const void* p) {
    uint32_t a;
    asm("{ .reg .u64 t; cvta.to.shared.u64 t, %1; cvt.u32.u64 %0, t; }" : "=r"(a) : "l"(p));
    return a;
}
__device__ __forceinline__ void ldsm_x4(uint32_t* r, uint32_t addr) {
    asm volatile("ldmatrix.sync.aligned.m8n8.x4.shared.b16 {%0,%1,%2,%3}, [%4];"
        : "=r"(r[0]), "=r"(r[1]), "=r"(r[2]), "=r"(r[3]) : "r"(addr));
}
__device__ __forceinline__ void ldsm_x4t(uint32_t* r, uint32_t addr) {
    asm volatile("ldmatrix.sync.aligned.m8n8.x4.trans.shared.b16 {%0,%1,%2,%3}, [%4];"
        : "=r"(r[0]), "=r"(r[1]), "=r"(r[2]), "=r"(r[3]) : "r"(addr));
}
__device__ __forceinline__ void mma16816(float* d, const uint32_t* a, const uint32_t* b) {
    asm volatile(
        "mma.sync.aligned.m16n8k16.row.col.f32.bf16.bf16.f32 "
        "{%0,%1,%2,%3}, {%4,%5,%6,%7}, {%8,%9}, {%0,%1,%2,%3};"
        : "+f"(d[0]), "+f"(d[1]), "+f"(d[2]), "+f"(d[3])
        : "r"(a[0]), "r"(a[1]), "r"(a[2]), "r"(a[3]), "r"(b[0]), "r"(b[1]));
}
__device__ __forceinline__ void cp16(uint32_t dst, const void* src) {
    asm volatile("cp.async.cg.shared.global [%0], [%1], 16;" :: "r"(dst), "l"(src));
}
#define CP_COMMIT() asm volatile("cp.async.commit_group;" ::: "memory")
#define CP_WAIT0()  asm volatile("cp.async.wait_group 0;" ::: "memory")

__device__ __forceinline__ uint32_t bf16_split2(float x0, float x1, uint32_t& lo_out) {
    __nv_bfloat16 h0 = __float2bfloat16(x0);
    __nv_bfloat16 h1 = __float2bfloat16(x1);
    __nv_bfloat16 l0 = __float2bfloat16(x0 - __bfloat162float(h0));
    __nv_bfloat16 l1 = __float2bfloat16(x1 - __bfloat162float(h1));
    lo_out = (uint32_t)__bfloat16_as_ushort(l0) | ((uint32_t)__bfloat16_as_ushort(l1) << 16);
    return (uint32_t)__bfloat16_as_ushort(h0) | ((uint32_t)__bfloat16_as_ushort(h1) << 16);
}

__device__ __forceinline__ float warp_max(float v) {
#pragma unroll
    for (int o = 16; o > 0; o >>= 1) v = fmaxf(v, __shfl_xor_sync(0xffffffffu, v, o));
    return v;
}
__device__ __forceinline__ float warp_sum(float v) {
#pragma unroll
    for (int o = 16; o > 0; o >>= 1) v += __shfl_xor_sync(0xffffffffu, v, o);
    return v;
}

// ---------------- fused weight prep (single launch, 360448 elements) ----------------
__global__ void prep_all(const float* __restrict__ m1, const float* __restrict__ r1w,
                         const float* __restrict__ u1, const float* __restrict__ m2,
                         const float* __restrict__ r2w, const float* __restrict__ u2,
                         unsigned char* __restrict__ wt) {
    int idx = blockIdx.x * 256 + threadIdx.x;
    if (idx >= 360448) return;
    float x; unsigned short* d; int l, losz;
    if (idx < 65536) {                       // upd1 [256][256]
        l = idx; x = u1[l]; d = (unsigned short*)(wt + OFF_UPD1); losz = 65536;
    } else if (idx < 98304) {                // msg2 [256][128]
        l = idx - 65536; x = m2[l]; d = (unsigned short*)(wt + OFF_MSG2); losz = 32768;
    } else if (idx < 131072) {               // rmsg2
        l = idx - 98304; x = r2w[l]; d = (unsigned short*)(wt + OFF_RMSG2); losz = 32768;
    } else if (idx < 163840) {               // upd2
        l = idx - 131072; x = u2[l]; d = (unsigned short*)(wt + OFF_UPD2); losz = 32768;
    } else if (idx < 294912) {               // wcat [128][1024]
        l = idx - 163840;
        int k = l >> 10, n = l & 1023;
        if (n < 256)      x = m1[k * 256 + n];
        else if (n < 512) x = m1[(128 + k) * 256 + (n - 256)];
        else if (n < 768) x = r1w[k * 256 + (n - 512)];
        else              x = r1w[(128 + k) * 256 + (n - 768)];
        d = (unsigned short*)(wt + OFF_WCAT); losz = 131072;
    } else {                                 // wec [128][512]
        l = idx - 294912;
        int k = l >> 9, n = l & 511;
        x = (n < 256) ? m1[(256 + k) * 256 + n] : r1w[(256 + k) * 256 + (n - 256)];
        d = (unsigned short*)(wt + OFF_WEC); losz = 65536;
    }
    __nv_bfloat16 hb = __float2bfloat16(x);
    __nv_bfloat16 lb = __float2bfloat16(x - __bfloat162float(hb));
    d[l]        = __bfloat16_as_ushort(hb);
    d[losz + l] = __bfloat16_as_ushort(lb);
}

// ---------------- encoder ----------------
__global__ void __launch_bounds__(128) encode16(const float* __restrict__ x,
                                                const float* __restrict__ W,
                                                const float* __restrict__ bias, int which) {
    __shared__ float sW[32 * 128];
    __shared__ float sx[16][32];
    int tid = threadIdx.x;
    int r0 = blockIdx.x * 16;
    for (int i = tid; i < 4096; i += 128) sW[i] = W[i];
    for (int i = tid; i < 512; i += 128) sx[i >> 5][i & 31] = x[r0 * 32 + i];
    __syncthreads();
    float b = bias[tid];
    float* dst = (which == 0) ? g_h : g_e;
#pragma unroll 4
    for (int rr = 0; rr < 16; rr++) {
        float acc = b;
#pragma unroll
        for (int k = 0; k < 32; k++) acc = fmaf(sx[rr][k], sW[k * 128 + tid], acc);
        dst[(size_t)(r0 + rr) * 128 + tid] = acc;
    }
}

__global__ void zero_agg_kernel() {
    int i = blockIdx.x * blockDim.x + threadIdx.x;
    if (i < cN * cD) g_agg[i] = 0.f;
}

// ---------------- pre_gemm: dense [32 x 128] @ [128 x 256-slice] -> fp32 ----------------
// W layout: bf16 hi [128][wcols] then lo; slice col base = blockIdx.y*256.
__global__ void __launch_bounds__(256, 2) pre_gemm(
    const float* __restrict__ xsrc, const unsigned char* __restrict__ w,
    int wRowB, int wLoOff, float* __restrict__ dst, int dstStride,
    const float* __restrict__ biasA, const float* __restrict__ biasB) {
    extern __shared__ __align__(16) unsigned char smem[];
    const uint32_t sb = smem_u32(smem);
    const int tid = threadIdx.x, lane = tid & 31, wid = tid >> 5;
    const int r0 = blockIdx.x * 32;
    const int cbk = blockIdx.y;
    const float* bias = (cbk == 0) ? biasA : biasB;

    // X: 32 rows x 128 cols -> bf16 hi/lo, stride 256B, swizzled
    for (int i = tid; i < 1024; i += 256) {
        int r = i >> 5, c4 = (i & 31) << 2;
        float4 v = *(const float4*)&xsrc[(size_t)(r0 + r) * 128 + c4];
        uint32_t lo0, hi0 = bf16_split2(v.x, v.y, lo0);
        uint32_t lo1, hi1 = bf16_split2(v.z, v.w, lo1);
        uint32_t o = (uint32_t)r * 256 + (((uint32_t)(c4 * 2)) ^ ((uint32_t)(r & 7) << 4));
        *(uint32_t*)(smem + o)            = hi0;
        *(uint32_t*)(smem + o + 4)        = hi1;
        *(uint32_t*)(smem + 8192 + o)     = lo0;
        *(uint32_t*)(smem + 8192 + o + 4) = lo1;
    }
    // W chunk 0 (32 k-rows x 256 cols, hi+lo)
    for (int i = tid; i < 2048; i += 256) {
        int comp = i >> 10, rr = (i >> 5) & 31, cc = i & 31;
        cp16(sb + 16384 + comp * 16384 + rr * 512 + ((cc * 16) ^ ((rr & 7) << 4)),
             w + (size_t)comp * wLoOff + (size_t)rr * wRowB + cbk * 512 + cc * 16);
    }
    CP_COMMIT();

    const int rg = (wid & 1) << 4;
    const int n0 = (wid >> 1) << 6;
    const int m_ = lane >> 3, r_ = lane & 7;
    const int arow = rg + ((m_ & 1) << 3) + r_;
    const int acol = (m_ >> 1) << 3;
    const int bRow = lane & 15, bAdd = (lane >> 4) << 3;
    const uint32_t aswz = (uint32_t)(arow & 7) << 4;
    const uint32_t bswz = (uint32_t)(bRow & 7) << 4;
    const uint32_t aHiB = sb + (uint32_t)arow * 256;
    const uint32_t aLoB = aHiB + 8192;

    float acc[8][4];
#pragma unroll
    for (int j = 0; j < 8; j++)
#pragma unroll
        for (int q = 0; q < 4; q++) acc[j][q] = 0.f;

    for (int c = 0; c < 4; c++) {
        CP_WAIT0();
        __syncthreads();
        if (c + 1 < 4) {
            const int nb = (c + 1) & 1;
            for (int i = tid; i < 2048; i += 256) {
                int comp = i >> 10, rr = (i >> 5) & 31, cc = i & 31;
                cp16(sb + 16384 + nb * 32768 + comp * 16384 + rr * 512 + ((cc * 16) ^ ((rr & 7) << 4)),
                     w + (size_t)comp * wLoOff + (size_t)((c + 1) * 32 + rr) * wRowB + cbk * 512 + cc * 16);
            }
            CP_COMMIT();
        }
        const uint32_t wb = sb + 16384 + (c & 1) * 32768;
#pragma unroll
        for (int kt = 0; kt < 2; kt++) {
            int kg = c * 32 + kt * 16;
            uint32_t aHi[4], aLo[4];
            uint32_t ac = ((uint32_t)((acol + kg) * 2)) ^ aswz;
            ldsm_x4(aHi, aHiB + ac);
            ldsm_x4(aLo, aLoB + ac);
            uint32_t bb = wb + (uint32_t)(kt * 16 + bRow) * 512;
#pragma unroll
            for (int j = 0; j < 4; j++) {
                uint32_t cbyte = ((uint32_t)((n0 + bAdd + j * 16) * 2)) ^ bswz;
                uint32_t bh[4], bl[4];
                ldsm_x4t(bh, bb + cbyte);
                ldsm_x4t(bl, bb + 16384 + cbyte);
                mma16816(acc[2 * j],     aHi, bh);
                mma16816(acc[2 * j + 1], aHi, bh + 2);
                mma16816(acc[2 * j],     aHi, bl);
                mma16816(acc[2 * j + 1], aHi, bl + 2);
                mma16816(acc[2 * j],     aLo, bh);
                mma16816(acc[2 * j + 1], aLo, bh + 2);
            }
        }
    }
    // epilogue: fp32 out (+optional bias)
    const int cb_ = n0 + (lane & 3) * 2;
    const int r1 = rg + (lane >> 2);
#pragma unroll
    for (int j = 0; j < 8; j++) {
        int cc = cb_ + j * 8;
        float b0 = bias ? __ldg(bias + cc) : 0.f;
        float b1v = bias ? __ldg(bias + cc + 1) : 0.f;
        size_t o0 = (size_t)(r0 + r1) * dstStride + cbk * 256 + cc;
        size_t o1 = (size_t)(r0 + r1 + 8) * dstStride + cbk * 256 + cc;
        dst[o0]     = acc[j][0] + b0;
        dst[o0 + 1] = acc[j][1] + b1v;
        dst[o1]     = acc[j][2] + b0;
        dst[o1 + 1] = acc[j][3] + b1v;
    }
}

// ---------------- edge2: gather-add-relu + stage2 GEMM, msg then rmsg ----------------
// MODE 0: atomicAdd f->g_agg[to], r->g_agg[from];  MODE 1: g_em = f + r
template <int MODE>
__global__ void __launch_bounds__(256, 3) edge2(
    const int* __restrict__ from_idx, const int* __restrict__ to_idx,
    const unsigned char* __restrict__ wt,
    const float* __restrict__ b2m, const float* __restrict__ b2r) {
    extern __shared__ __align__(16) unsigned char smem[];
    const uint32_t sb = smem_u32(smem);
    const int tid = threadIdx.x, lane = tid & 31, wid = tid >> 5;
    const int e0 = blockIdx.x * 32;
    int* sF = (int*)(smem + e2IDX);
    int* sT = sF + 32;
    if (tid < 32) { sF[tid] = from_idx[e0 + tid]; sT[tid] = to_idx[e0 + tid]; }
    __syncthreads();

    const int rg = (wid & 1) << 4;
    const int n2 = (wid >> 1) << 5;
    const int m_ = lane >> 3, r_ = lane & 7;
    const int arow = rg + ((m_ & 1) << 3) + r_;
    const int acol = (m_ >> 1) << 3;
    const int bRow = lane & 15, bAdd = (lane >> 4) << 3;
    const uint32_t aswz = (uint32_t)(arow & 7) << 4;
    const uint32_t bswz = (uint32_t)(bRow & 7) << 4;
    const uint32_t aHiB = sb + (uint32_t)arow * 512;
    const uint32_t aLoB = aHiB + 16384;

#pragma unroll
    for (int ph = 0; ph < 2; ph++) {
        const unsigned char* w2t = wt + (ph ? OFF_RMSG2 : OFF_MSG2);
        const float* b2 = ph ? b2r : b2m;
        if (ph) __syncthreads();             // hidden + W2 bufs safe to reuse
        // issue W2 chunk 0
        for (int i = tid; i < 1024; i += 256) {
            int comp = i >> 9, rr = (i >> 4) & 31, cc = i & 15;
            cp16(sb + e2W2B + comp * 8192 + rr * 256 + ((cc * 16) ^ ((rr & 7) << 4)),
                 w2t + (size_t)comp * 65536 + (size_t)rr * 256 + cc * 16);
        }
        CP_COMMIT();
        // gather hidden = relu(P[a] + P[b] + Ec) -> bf16 hi/lo (stride 512B)
        for (int i = tid; i < 2048; i += 256) {
            int r = i >> 6, c4 = (i & 63) << 2;
            int ia = ph ? sT[r] : sF[r];
            int ib = ph ? sF[r] : sT[r];
            const float4 fa = *(const float4*)&g_pre[(size_t)ia * 1024 + ph * 512 + c4];
            const float4 fb = *(const float4*)&g_pre[(size_t)ib * 1024 + ph * 512 + 256 + c4];
            const float4 fe = *(const float4*)&g_epre[(size_t)(e0 + r) * 512 + ph * 256 + c4];
            float v0 = fmaxf(fa.x + fb.x + fe.x, 0.f);
            float v1 = fmaxf(fa.y + fb.y + fe.y, 0.f);
            float v2 = fmaxf(fa.z + fb.z + fe.z, 0.f);
            float v3 = fmaxf(fa.w + fb.w + fe.w, 0.f);
            uint32_t lo0, hi0 = bf16_split2(v0, v1, lo0);
            uint32_t lo1, hi1 = bf16_split2(v2, v3, lo1);
            uint32_t o = (uint32_t)r * 512 + (((uint32_t)(c4 * 2)) ^ ((uint32_t)(r & 7) << 4));
            *(uint32_t*)(smem + o)             = hi0;
            *(uint32_t*)(smem + o + 4)         = hi1;
            *(uint32_t*)(smem + 16384 + o)     = lo0;
            *(uint32_t*)(smem + 16384 + o + 4) = lo1;
        }
        // stage2: 8 chunks of K=32
        float acc2[4][4];
#pragma unroll
        for (int j = 0; j < 4; j++)
#pragma unroll
            for (int q = 0; q < 4; q++) acc2[j][q] = 0.f;
        for (int c = 0; c < 8; c++) {
            CP_WAIT0();
            __syncthreads();
            if (c + 1 < 8) {
                const int nb = (c + 1) & 1;
                for (int i = tid; i < 1024; i += 256) {
                    int comp = i >> 9, rr = (i >> 4) & 31, cc = i & 15;
                    cp16(sb + e2W2B + nb * 16384 + comp * 8192 + rr * 256 + ((cc * 16) ^ ((rr & 7) << 4)),
                         w2t + (size_t)comp * 65536 + (size_t)((c + 1) * 32 + rr) * 256 + cc * 16);
                }
                CP_COMMIT();
            }
            const uint32_t wb2 = sb + e2W2B + (c & 1) * 16384;
#pragma unroll
            for (int kt = 0; kt < 2; kt++) {
                int kg = c * 32 + kt * 16;
                uint32_t aHi[4], aLo[4];
                uint32_t ac = ((uint32_t)((acol + kg) * 2)) ^ aswz;
                ldsm_x4(aHi, aHiB + ac);
                ldsm_x4(aLo, aLoB + ac);
                uint32_t bb = wb2 + (uint32_t)(kt * 16 + bRow) * 256;
#pragma unroll
                for (int j = 0; j < 2; j++) {
                    uint32_t cbyte = ((uint32_t)((n2 + bAdd + j * 16) * 2)) ^ bswz;
                    uint32_t bh[4], bl[4];
                    ldsm_x4t(bh, bb + cbyte);
                    ldsm_x4t(bl, bb + 8192 + cbyte);
                    mma16816(acc2[2 * j],     aHi, bh);
                    mma16816(acc2[2 * j + 1], aHi, bh + 2);
                    mma16816(acc2[2 * j],     aHi, bl);
                    mma16816(acc2[2 * j + 1], aHi, bl + 2);
                    mma16816(acc2[2 * j],     aLo, bh);
                    mma16816(acc2[2 * j + 1], aLo, bh + 2);
                }
            }
        }
        // epilogue
        const int cb_ = n2 + (lane & 3) * 2;
        const int r1 = rg + (lane >> 2);
#pragma unroll
        for (int j = 0; j < 4; j++) {
            int cc = cb_ + j * 8;
            float b0 = __ldg(b2 + cc), b1v = __ldg(b2 + cc + 1);
            float v00 = acc2[j][0] + b0, v01 = acc2[j][1] + b1v;
            float v10 = acc2[j][2] + b0, v11 = acc2[j][3] + b1v;
            if (MODE == 0) {
                int nA = ph ? sF[r1] : sT[r1];
                int nB = ph ? sF[r1 + 8] : sT[r1 + 8];
                atomicAdd(&g_agg[(size_t)nA * cD + cc],     v00);
                atomicAdd(&g_agg[(size_t)nA * cD + cc + 1], v01);
                atomicAdd(&g_agg[(size_t)nB * cD + cc],     v10);
                atomicAdd(&g_agg[(size_t)nB * cD + cc + 1], v11);
            } else {
                float* d0 = &g_em[(size_t)(e0 + r1) * cD + cc];
                float* d1 = &g_em[(size_t)(e0 + r1 + 8) * cD + cc];
                if (ph == 0) {
                    d0[0] = v00; d0[1] = v01;
                    d1[0] = v10; d1[1] = v11;
                } else {
                    d0[0] += v00; d0[1] += v01;
                    d1[0] += v10; d1[1] += v11;
                }
            }
        }
    }
}

// ---------------- run_mlp (R8, used by upd only) ----------------
template <int K1, int XST, int XHI, int XLO, int WB, int W2B>
__device__ __forceinline__ void run_mlp(
    unsigned char* smem, uint32_t sb,
    const unsigned char* __restrict__ w1t, const float* __restrict__ b1p,
    const unsigned char* __restrict__ w2t,
    int tid, int lane, int wid, float out[4][4]) {
    const int rg = (wid & 1) << 4;
    const int n0 = (wid >> 1) << 6;
    const int n2 = (wid >> 1) << 5;
    const int m_ = lane >> 3, r_ = lane & 7;
    const int arow = rg + ((m_ & 1) << 3) + r_;
    const int acol = (m_ >> 1) << 3;
    const int bRow = lane & 15;
    const int bAdd = (lane >> 4) << 3;
    const uint32_t aswz = (uint32_t)(arow & 7) << 4;
    const uint32_t aHiB = sb + XHI + (uint32_t)arow * XST;
    const uint32_t aLoB = sb + XLO + (uint32_t)arow * XST;
    const uint32_t bswz = (uint32_t)(bRow & 7) << 4;

    float acc[8][4];
#pragma unroll
    for (int j = 0; j < 8; j++)
#pragma unroll
        for (int q = 0; q < 4; q++) acc[j][q] = 0.f;

    constexpr int NC1 = K1 / 32;
    for (int i = tid; i < 2048; i += 256) {
        int comp = i >> 10, rr = (i >> 5) & 31, cc = i & 31;
        cp16(sb + WB + comp * 16384 + rr * 512 + ((cc * 16) ^ ((rr & 7) << 4)),
             w1t + (size_t)comp * (K1 * 512) + (size_t)rr * 512 + cc * 16);
    }
    CP_COMMIT();

    for (int c = 0; c < NC1; c++) {
        CP_WAIT0();
        __syncthreads();
        if (c + 1 < NC1) {
            const int nb = (c + 1) & 1;
            for (int i = tid; i < 2048; i += 256) {
                int comp = i >> 10, rr = (i >> 5) & 31, cc = i & 31;
                cp16(sb + WB + nb * 32768 + comp * 16384 + rr * 512 + ((cc * 16) ^ ((rr & 7) << 4)),
                     w1t + (size_t)comp * (K1 * 512) + (size_t)((c + 1) * 32 + rr) * 512 + cc * 16);
            }
            CP_COMMIT();
        }
        const uint32_t wb1 = sb + WB + (c & 1) * 32768;
#pragma unroll
        for (int kt = 0; kt < 2; kt++) {
            int kg = c * 32 + kt * 16;
            uint32_t aHi[4], aLo[4];
            uint32_t ac = ((uint32_t)((acol + kg) * 2)) ^ aswz;
            ldsm_x4(aHi, aHiB + ac);
            ldsm_x4(aLo, aLoB + ac);
            uint32_t bb = wb1 + (uint32_t)(kt * 16 + bRow) * 512;
#pragma unroll
            for (int j = 0; j < 4; j++) {
                uint32_t cbyte = ((uint32_t)((n0 + bAdd + j * 16) * 2)) ^ bswz;
                uint32_t bh[4], bl[4];
                ldsm_x4t(bh, bb + cbyte);
                ldsm_x4t(bl, bb + 16384 + cbyte);
                mma16816(acc[2 * j],     aHi, bh);
                mma16816(acc[2 * j + 1], aHi, bh + 2);
                mma16816(acc[2 * j],     aHi, bl);
                mma16816(acc[2 * j + 1], aHi, bl + 2);
                mma16816(acc[2 * j],     aLo, bh);
                mma16816(acc[2 * j + 1], aLo, bh + 2);
            }
        }
    }
    __syncthreads();

    {
        int cb = n0 + (lane & 3) * 2;
        int r1 = rg + (lane >> 2);
        uint32_t s1 = (uint32_t)(r1 & 7) << 4;
#pragma unroll
        for (int j = 0; j < 8; j++) {
            int cc = cb + j * 8;
            float b0 = __ldg(b1p + cc), b1v = __ldg(b1p + cc + 1);
            float v00 = fmaxf(acc[j][0] + b0, 0.f), v01 = fmaxf(acc[j][1] + b1v, 0.f);
            float v10 = fmaxf(acc[j][2] + b0, 0.f), v11 = fmaxf(acc[j][3] + b1v, 0.f);
            uint32_t lo0, hi0 = bf16_split2(v00, v01, lo0);
            uint32_t lo1, hi1 = bf16_split2(v10, v11, lo1);
            uint32_t o1 = ((uint32_t)(cc * 2)) ^ s1;
            *(uint32_t*)(smem + WB + r1 * 512 + o1)               = hi0;
            *(uint32_t*)(smem + WB + 16384 + r1 * 512 + o1)       = lo0;
            *(uint32_t*)(smem + WB + (r1 + 8) * 512 + o1)         = hi1;
            *(uint32_t*)(smem + WB + 16384 + (r1 + 8) * 512 + o1) = lo1;
        }
    }

    float acc2[4][4];
#pragma unroll
    for (int j = 0; j < 4; j++)
#pragma unroll
        for (int q = 0; q < 4; q++) acc2[j][q] = 0.f;
    const uint32_t a2HiB = sb + WB + (uint32_t)arow * 512;
    const uint32_t a2LoB = a2HiB + 16384;

    for (int i = tid; i < 1024; i += 256) {
        int comp = i >> 9, rr = (i >> 4) & 31, cc = i & 15;
        cp16(sb + W2B + comp * 8192 + rr * 256 + ((cc * 16) ^ ((rr & 7) << 4)),
             w2t + (size_t)comp * 65536 + (size_t)rr * 256 + cc * 16);
    }
    CP_COMMIT();

    for (int c = 0; c < 8; c++) {
        CP_WAIT0();
        __syncthreads();
        if (c + 1 < 8) {
            const int nb = (c + 1) & 1;
            for (int i = tid; i < 1024; i += 256) {
                int comp = i >> 9, rr = (i >> 4) & 31, cc = i & 15;
                cp16(sb + W2B + nb * 16384 + comp * 8192 + rr * 256 + ((cc * 16) ^ ((rr & 7) << 4)),
                     w2t + (size_t)comp * 65536 + (size_t)((c + 1) * 32 + rr) * 256 + cc * 16);
            }
            CP_COMMIT();
        }
        const uint32_t wb2 = sb + W2B + (c & 1) * 16384;
#pragma unroll
        for (int kt = 0; kt < 2; kt++) {
            int kg = c * 32 + kt * 16;
            uint32_t aHi[4], aLo[4];
            uint32_t ac = ((uint32_t)((acol + kg) * 2)) ^ aswz;
            ldsm_x4(aHi, a2HiB + ac);
            ldsm_x4(aLo, a2LoB + ac);
            uint32_t bb = wb2 + (uint32_t)(kt * 16 + bRow) * 256;
#pragma unroll
            for (int j = 0; j < 2; j++) {
                uint32_t cbyte = ((uint32_t)((n2 + bAdd + j * 16) * 2)) ^ bswz;
                uint32_t bh[4], bl[4];
                ldsm_x4t(bh, bb + cbyte);
                ldsm_x4t(bl, bb + 8192 + cbyte);
                mma16816(acc2[2 * j],     aHi, bh);
                mma16816(acc2[2 * j + 1], aHi, bh + 2);
                mma16816(acc2[2 * j],     aHi, bl);
                mma16816(acc2[2 * j + 1], aHi, bl + 2);
                mma16816(acc2[2 * j],     aLo, bh);
                mma16816(acc2[2 * j + 1], aLo, bh + 2);
            }
        }
    }
    __syncthreads();
#pragma unroll
    for (int j = 0; j < 4; j++)
#pragma unroll
        for (int q = 0; q < 4; q++) out[j][q] = acc2[j][q];
}

// ---------------- upd kernel: h += mlp([agg, h]) ----------------
__global__ void __launch_bounds__(256, 2) upd_mlp(
    const unsigned char* __restrict__ wt,
    const float* __restrict__ b1p, const float* __restrict__ b2p) {
    extern __shared__ __align__(16) unsigned char smem[];
    const uint32_t sb = smem_u32(smem);
    const int tid = threadIdx.x, lane = tid & 31, wid = tid >> 5;
    const int e0 = blockIdx.x * 32;

    for (int i = tid; i < 2048; i += 256) {
        int r = i >> 6, q = i & 63;
        int seg = q >> 5, c4 = (q & 31) << 2;
        const float* src = (seg == 0 ? g_agg : g_h) + (size_t)(e0 + r) * cD + c4;
        float4 v = *(const float4*)src;
        int col = seg * 128 + c4;
        uint32_t lo0, hi0 = bf16_split2(v.x, v.y, lo0);
        uint32_t lo1, hi1 = bf16_split2(v.z, v.w, lo1);
        uint32_t o = (uint32_t)r * 512 + (((uint32_t)(col * 2)) ^ ((uint32_t)(r & 7) << 4));
        *(uint32_t*)(smem + uX_HI + o)     = hi0;
        *(uint32_t*)(smem + uX_HI + o + 4) = hi1;
        *(uint32_t*)(smem + uX_LO + o)     = lo0;
        *(uint32_t*)(smem + uX_LO + o + 4) = lo1;
    }

    float oacc[4][4];
    run_mlp<256, 512, uX_HI, uX_LO, uWB, uW2B>(smem, sb, wt + OFF_UPD1, b1p,
                                               wt + OFF_UPD2, tid, lane, wid, oacc);

    const int rg = (wid & 1) << 4;
    const int n2 = (wid >> 1) << 5;
    const int cb = n2 + (lane & 3) * 2;
    const int r1 = rg + (lane >> 2);
#pragma unroll
    for (int j = 0; j < 4; j++) {
        int cc = cb + j * 8;
        float b0 = __ldg(b2p + cc), b1v = __ldg(b2p + cc + 1);
        g_h[(size_t)(e0 + r1) * cD + cc]         += oacc[j][0] + b0;
        g_h[(size_t)(e0 + r1) * cD + cc + 1]     += oacc[j][1] + b1v;
        g_h[(size_t)(e0 + r1 + 8) * cD + cc]     += oacc[j][2] + b0;
        g_h[(size_t)(e0 + r1 + 8) * cD + cc + 1] += oacc[j][3] + b1v;
    }
}

// ---------------- SK head ----------------
__global__ void __launch_bounds__(256) sk_kernel(
    const float* __restrict__ w1p, const float* __restrict__ b1p,
    const float* __restrict__ w2p, const float* __restrict__ b2p,
    const int* __restrict__ qs, const int* __restrict__ cs) {
    int t = threadIdx.x;
    int lr = t >> 6, j = t & 63;
    int row = blockIdx.x * 4 + lr;
    int b = row >> 6, sp = row & 63, s = sp >> 5, p = sp & 31;
    __shared__ float sx[4][128];
    __shared__ float sh[4][64];
    {
        bool valid = p < cNPG;
        int node = (b * 2 + s) * cNPG + p;
        sx[lr][j]      = valid ? g_h[node * cD + j]      : 0.f;
        sx[lr][j + 64] = valid ? g_h[node * cD + j + 64] : 0.f;
    }
    __syncthreads();
    float a = b1p[j];
#pragma unroll
    for (int k = 0; k < 128; k++) a = fmaf(sx[lr][k], w1p[k * 64 + j], a);
    sh[lr][j] = fmaxf(a, 0.f);
    __syncthreads();
    float o = b2p[j];
#pragma unroll
    for (int k = 0; k < 64; k++) o = fmaf(sh[lr][k], w2p[k * 64 + j], o);
    int size = (s == 0) ? qs[b] : cs[b];
    if (p >= size) o = 0.f;
    g_tqc[row * 64 + j] = o;
}

// ---------------- node scores + Sinkhorn ----------------
__global__ void __launch_bounds__(1024) node_plan_kernel() {
    int b = blockIdx.x;
    int tid = threadIdx.x;
    __shared__ float smq[32][65];
    __shared__ float smc[32][65];
    __shared__ float la[32 * 33];
    for (int idx = tid; idx < 2048; idx += 1024) {
        int r = idx >> 6, d = idx & 63;
        smq[r][d] = g_tqc[b * 4096 + idx];
        smc[r][d] = g_tqc[b * 4096 + 2048 + idx];
    }
    __syncthreads();
    int q = tid >> 5, c = tid & 31;
    float v = 0.f;
#pragma unroll
    for (int d = 0; d < 64; d++) v = fmaf(smq[q][d], smc[c][d], v);
    v *= 10.f;
    {
        float m = warp_max(v);
        float sum = warp_sum(__expf(v - m));
        v -= m + __logf(sum);
        la[q * 33 + c] = v;
        __syncthreads();
        float u = la[c * 33 + q];
        float s = warp_sum(__expf(u));
        u -= __logf(s);
        la[c * 33 + q] = u;
        __syncthreads();
        v = la[q * 33 + c];
    }
    for (int it = 1; it < 20; it++) {
        float s = warp_sum(__expf(v));
        v -= __logf(s);
        la[q * 33 + c] = v;
        __syncthreads();
        float u = la[c * 33 + q];
        s = warp_sum(__expf(u));
        u -= __logf(s);
        la[c * 33 + q] = u;
        __syncthreads();
        v = la[q * 33 + c];
    }
    g_plan[b * 1024 + q * 32 + c] = __expf(v);
}

// ---------------- node alignment ----------------
__global__ void __launch_bounds__(256) node_align_kernel(float* __restrict__ out) {
    int b = blockIdx.x, tid = threadIdx.x;
    __shared__ float sp_[32 * 32];
    __shared__ float scn[32][128];
    __shared__ float red[8];
    for (int idx = tid; idx < 1024; idx += 256) sp_[idx] = g_plan[b * 1024 + idx];
    for (int idx = tid; idx < 4096; idx += 256) {
        int p = idx >> 7, d = idx & 127;
        scn[p][d] = (p < cNPG) ? g_h[((b * 2 + 1) * cNPG + p) * cD + d] : 0.f;
    }
    __syncthreads();
    float local = 0.f;
    for (int idx = tid; idx < 4096; idx += 256) {
        int q = idx >> 7, d = idx & 127;
        float pc = 0.f;
#pragma unroll
        for (int c = 0; c < 32; c++) pc = fmaf(sp_[q * 32 + c], scn[c][d], pc);
        float qv = (q < cNPG) ? g_h[((b * 2) * cNPG + q) * cD + d] : 0.f;
        local += fmaxf(qv - pc, 0.f);
    }
    local = warp_sum(local);
    if ((tid & 31) == 0) red[tid >> 5] = local;
    __syncthreads();
    if (tid == 0) {
        float tot = 0.f;
        for (int i = 0; i < 8; i++) tot += red[i];
        out[b] = -tot;
    }
}

// ---------------- edge kron + Sinkhorn + alignment ----------------
__global__ void __launch_bounds__(1024) edge_align_kernel(
    const int* __restrict__ from_idx, const int* __restrict__ to_idx,
    float* __restrict__ out) {
    int b = blockIdx.x, tid = threadIdx.x;
    __shared__ float T[32 * 32];
    __shared__ float la[64][65];
    __shared__ int qf[64], qt[64], cf[64], ct[64];
    __shared__ float red[32];

    T[tid & 1023] = g_plan[b * 1024 + (tid & 1023)];
    if (tid < 64) {
        qf[tid] = from_idx[b * 128 + tid] % cNPG;
        qt[tid] = to_idx[b * 128 + tid] % cNPG;
        cf[tid] = from_idx[b * 128 + 64 + tid] % cNPG;
        ct[tid] = to_idx[b * 128 + 64 + tid] % cNPG;
    }
    __syncthreads();
    for (int idx = tid; idx < 4096; idx += 1024) {
        int i = idx >> 6, j = idx & 63;
        float s = T[qf[i] * 32 + cf[j]] * T[qt[i] * 32 + ct[j]]
                + T[qf[i] * 32 + ct[j]] * T[qt[i] * 32 + cf[j]];
        la[i][j] = s * 10.f;
    }
    __syncthreads();
    int w = tid >> 5, l = tid & 31;
    for (int it = 0; it < 20; it++) {
#pragma unroll
        for (int rr_ = 0; rr_ < 2; rr_++) {
            int rr = w + rr_ * 32;
            float v0 = la[rr][l], v1 = la[rr][l + 32];
            float s = warp_sum(__expf(v0) + __expf(v1));
            float lse = __logf(s);
            la[rr][l] = v0 - lse;
            la[rr][l + 32] = v1 - lse;
        }
        __syncthreads();
#pragma unroll
        for (int cc_ = 0; cc_ < 2; cc_++) {
            int cc = w + cc_ * 32;
            float v0 = la[l][cc], v1 = la[l + 32][cc];
            float s = warp_sum(__expf(v0) + __expf(v1));
            float lse = __logf(s);
            la[l][cc] = v0 - lse;
            la[l + 32][cc] = v1 - lse;
        }
        __syncthreads();
    }
    for (int idx = tid; idx < 4096; idx += 1024) {
        int i = idx >> 6, j = idx & 63;
        la[i][j] = __expf(la[i][j]);
    }
    __syncthreads();
    float local = 0.f;
    for (int idx = tid; idx < 8192; idx += 1024) {
        int i = idx >> 7, d = idx & 127;
        const float* ce = &g_em[(b * 128 + 64) * cD + d];
        float pc = 0.f;
#pragma unroll
        for (int j = 0; j < 64; j++) pc = fmaf(la[i][j], ce[j * cD], pc);
        float qv = g_em[(b * 128 + i) * cD + d];
        local += fmaxf(qv - pc, 0.f);
    }
    local = warp_sum(local);
    if (l == 0) red[w] = local;
    __syncthreads();
    if (tid == 0) {
        float tot = 0.f;
        for (int i = 0; i < 32; i++) tot += red[i];
        out[b] += -0.9f * tot;
    }
}

// ---------------- launch ----------------
extern "C" void kernel_launch(void* const* d_in, const int* in_sizes, int n_in,
                              void* d_out, int out_size) {
    const float* nf      = (const float*)d_in[0];
    const float* ef      = (const float*)d_in[1];
    const float* enc_nw  = (const float*)d_in[2];
    const float* enc_nb  = (const float*)d_in[3];
    const float* enc_ew  = (const float*)d_in[4];
    const float* enc_eb  = (const float*)d_in[5];
    const float* msg_w1  = (const float*)d_in[6];
    const float* msg_b1  = (const float*)d_in[7];
    const float* msg_w2  = (const float*)d_in[8];
    const float* msg_b2  = (const float*)d_in[9];
    const float* rmsg_w1 = (const float*)d_in[10];
    const float* rmsg_b1 = (const float*)d_in[11];
    const float* rmsg_w2 = (const float*)d_in[12];
    const float* rmsg_b2 = (const float*)d_in[13];
    const float* upd_w1  = (const float*)d_in[14];
    const float* upd_b1  = (const float*)d_in[15];
    const float* upd_w2  = (const float*)d_in[16];
    const float* upd_b2  = (const float*)d_in[17];
    const float* sk_w1   = (const float*)d_in[18];
    const float* sk_b1   = (const float*)d_in[19];
    const float* sk_w2   = (const float*)d_in[20];
    const float* sk_b2   = (const float*)d_in[21];
    const int* from_idx  = (const int*)d_in[22];
    const int* to_idx    = (const int*)d_in[23];
    const int* qs        = (const int*)d_in[24];
    const int* cs        = (const int*)d_in[25];
    float* out = (float*)d_out;

    unsigned char* wt = nullptr;
    float *d_gh = nullptr, *d_ge = nullptr, *d_gpre = nullptr, *d_gepre = nullptr;
    cudaGetSymbolAddress((void**)&wt, g_wt);
    cudaGetSymbolAddress((void**)&d_gh, g_h);
    cudaGetSymbolAddress((void**)&d_ge, g_e);
    cudaGetSymbolAddress((void**)&d_gpre, g_pre);
    cudaGetSymbolAddress((void**)&d_gepre, g_epre);

    cudaFuncSetAttribute(pre_gemm, cudaFuncAttributeMaxDynamicSharedMemorySize, SMEM_PRE);
    cudaFuncSetAttribute(edge2<0>, cudaFuncAttributeMaxDynamicSharedMemorySize, SMEM_EDGE2);
    cudaFuncSetAttribute(edge2<1>, cudaFuncAttributeMaxDynamicSharedMemorySize, SMEM_EDGE2);
    cudaFuncSetAttribute(upd_mlp,  cudaFuncAttributeMaxDynamicSharedMemorySize, SMEM_UPD);

    // weight prep (single fused launch)
    prep_all<<<1408, 256>>>(msg_w1, rmsg_w1, upd_w1, msg_w2, rmsg_w2, upd_w2, wt);

    // encode
    encode16<<<cN / 16, 128>>>(nf, enc_nw, enc_nb, 0);
    encode16<<<cE / 16, 128>>>(ef, enc_ew, enc_eb, 1);

    // one-time edge precompute: g_epre = e @ [W1c|R1c] + [b1m|b1r]
    pre_gemm<<<dim3(cE / 32, 2), 256, SMEM_PRE>>>(d_ge, wt + OFF_WEC, 1024, 131072,
                                                  d_gepre, 512, msg_b1, rmsg_b1);

    // 3 message-passing steps
    for (int step = 0; step < 3; step++) {
        zero_agg_kernel<<<(cN * cD + 1023) / 1024, 1024>>>();
        pre_gemm<<<dim3(cN / 32, 4), 256, SMEM_PRE>>>(d_gh, wt + OFF_WCAT, 2048, 262144,
                                                      d_gpre, 1024, nullptr, nullptr);
        edge2<0><<<cE / 32, 256, SMEM_EDGE2>>>(from_idx, to_idx, wt, msg_b2, rmsg_b2);
        upd_mlp<<<cN / 32, 256, SMEM_UPD>>>(wt, upd_b1, upd_b2);
    }

    // final messages -> em = f + r
    pre_gemm<<<dim3(cN / 32, 4), 256, SMEM_PRE>>>(d_gh, wt + OFF_WCAT, 2048, 262144,
                                                  d_gpre, 1024, nullptr, nullptr);
    edge2<1><<<cE / 32, 256, SMEM_EDGE2>>>(from_idx, to_idx, wt, msg_b2, rmsg_b2);

    // SK head, node plan, node align, edge align
    sk_kernel<<<cB * 2 * cMAXN / 4, 256>>>(sk_w1, sk_b1, sk_w2, sk_b2, qs, cs);
    node_plan_kernel<<<cB, 1024>>>();
    node_align_kernel<<<cB, 256>>>(out);
    edge_align_kernel<<<cB, 1024>>>(from_idx, to_idx, out);
}